// round 11
// baseline (speedup 1.0000x reference)
#include <cuda_runtime.h>
#include <cuda_fp16.h>
#include <math.h>
#include <stdint.h>

// ---------------- problem constants ----------------
#define BSZ    2
#define SEQ    2048
#define DMODEL 1024
#define NHEADS 16
#define HDIM   64
#define FFDIM  4096
#define MROWS (BSZ*SEQ)          // 4096
#define QKVW  (3*DMODEL)         // 3072
#define LN_EPS 1e-5f
#define QSCALE 0.18033688011112042f   // 0.125 * log2(e)

// ---------------- scratch (device globals; no allocs) ----------------
__device__ float  g_x2  [MROWS*DMODEL];
__device__ float  g_bqkv[QKVW];
__device__ __half g_qkvh[(size_t)MROWS*QKVW];
__device__ __half g_ah[(size_t)MROWS*DMODEL];        // activations (fp16)
__device__ __half g_hh[(size_t)MROWS*FFDIM];         // FFN hidden (fp16)
__device__ __half g_wh[(size_t)12*1024*1024];        // all weights fp16 (24MB)

// ---------------- LayerNorm -> fp16 directly ----------------
__global__ __launch_bounds__(256) void ln_h16(const float* __restrict__ x,
                                              const float* __restrict__ g,
                                              const float* __restrict__ b,
                                              __half* __restrict__ ah) {
    int row = blockIdx.x;
    int t   = threadIdx.x;
    const float4 v = ((const float4*)(x + (size_t)row * DMODEL))[t];
    float s  = v.x + v.y + v.z + v.w;
    float ss = v.x*v.x + v.y*v.y + v.z*v.z + v.w*v.w;
    #pragma unroll
    for (int o = 16; o; o >>= 1) {
        s  += __shfl_xor_sync(0xffffffffu, s,  o);
        ss += __shfl_xor_sync(0xffffffffu, ss, o);
    }
    __shared__ float rs[8], rss[8];
    if ((t & 31) == 0) { rs[t >> 5] = s; rss[t >> 5] = ss; }
    __syncthreads();
    float S = 0.f, SS = 0.f;
    #pragma unroll
    for (int i = 0; i < 8; i++) { S += rs[i]; SS += rss[i]; }
    float mean = S * (1.f / DMODEL);
    float var  = SS * (1.f / DMODEL) - mean * mean;
    float rstd = rsqrtf(var + LN_EPS);
    const float4 gv = ((const float4*)g)[t];
    const float4 bv = ((const float4*)b)[t];
    float o0 = (v.x - mean) * rstd * gv.x + bv.x;
    float o1 = (v.y - mean) * rstd * gv.y + bv.y;
    float o2 = (v.z - mean) * rstd * gv.z + bv.z;
    float o3 = (v.w - mean) * rstd * gv.w + bv.w;
    __half2* ph = (__half2*)(ah + (size_t)row * DMODEL);
    ph[t*2]   = __floats2half2_rn(o0, o1);
    ph[t*2+1] = __floats2half2_rn(o2, o3);
}

// ---------------- fp32 -> fp16 convert (weights), 8 elems/thread ----------------
__global__ __launch_bounds__(256) void cvt16(const float* __restrict__ src,
                                             __half* __restrict__ dst) {
    size_t i = ((size_t)blockIdx.x * 256 + threadIdx.x) * 8;
    const float4 f0 = *(const float4*)(src + i);
    const float4 f1 = *(const float4*)(src + i + 4);
    __half2 h0 = __floats2half2_rn(f0.x, f0.y);
    __half2 h1 = __floats2half2_rn(f0.z, f0.w);
    __half2 h2 = __floats2half2_rn(f1.x, f1.y);
    __half2 h3 = __floats2half2_rn(f1.z, f1.w);
    uint4 ph;
    ph.x = *(uint32_t*)&h0; ph.y = *(uint32_t*)&h1;
    ph.z = *(uint32_t*)&h2; ph.w = *(uint32_t*)&h3;
    *(uint4*)(dst + i) = ph;
}

__global__ void pack_bias(const float* __restrict__ a, const float* __restrict__ b,
                          const float* __restrict__ c, float* __restrict__ out) {
    int i = blockIdx.x * 256 + threadIdx.x;
    float v = (i < 1024) ? a[i] : (i < 2048) ? b[i - 1024] : c[i - 2048];
    out[i] = v;
}

// ---------------- PTX helpers ----------------
#define CP16(sa, ga) asm volatile("cp.async.cg.shared.global [%0], [%1], 16;\n" :: "r"(sa), "l"(ga))
#define COMMIT() asm volatile("cp.async.commit_group;\n" ::)
#define LDMX4(r0,r1,r2,r3,addr) asm volatile( \
    "ldmatrix.sync.aligned.m8n8.x4.shared.b16 {%0,%1,%2,%3}, [%4];" \
    : "=r"(r0), "=r"(r1), "=r"(r2), "=r"(r3) : "r"(addr))
#define LDMX4T(r0,r1,r2,r3,addr) asm volatile( \
    "ldmatrix.sync.aligned.m8n8.x4.trans.shared.b16 {%0,%1,%2,%3}, [%4];" \
    : "=r"(r0), "=r"(r1), "=r"(r2), "=r"(r3) : "r"(addr))
#define MMA16816(d, a0,a1,a2,a3, b0,b1) asm volatile( \
    "mma.sync.aligned.m16n8k16.row.col.f32.f16.f16.f32 " \
    "{%0,%1,%2,%3}, {%4,%5,%6,%7}, {%8,%9}, {%0,%1,%2,%3};" \
    : "+f"(d[0]), "+f"(d[1]), "+f"(d[2]), "+f"(d[3]) \
    : "r"(a0), "r"(a1), "r"(a2), "r"(a3), "r"(b0), "r"(b1))

__device__ __forceinline__ float ex2f(float x) {
    float y;
    asm("ex2.approx.f32 %0, %1;" : "=f"(y) : "f"(x));
    return y;
}

// ---------------- single-term fp16 GEMM (BK=64, warp tile 64x64, 3-stage) ----------------
#define GSTRIDE 72
#define TILE_H  (128 * GSTRIDE)
#define STAGE_H (2 * TILE_H)
#define NSTAGE  3
#define GSMEM_BYTES (NSTAGE * STAGE_H * 2)   // 110592

__device__ __forceinline__ void g_load_stage(uint32_t smBase, int stg,
                                             const __half* gA, const __half* gB,
                                             int K, int k0, int tid) {
    const uint32_t sb = smBase + (uint32_t)(stg * STAGE_H * 2);
    #pragma unroll
    for (int i = 0; i < 8; i++) {
        const int idx = tid + i * 128;          // [0,1024)
        const int r = idx >> 3, sg = (idx & 7) * 8;
        const uint32_t so = (uint32_t)((r * GSTRIDE + sg) << 1);
        const size_t go = (size_t)r * K + k0 + sg;
        CP16(sb + so,              gA + go);
        CP16(sb + TILE_H * 2 + so, gB + go);
    }
    COMMIT();
}

// epi: 2 = bias+residual -> float C ; 3 = bias (+Q-scale for col<1024) -> half Ch ;
//      4 = bias+GELU -> half Ch
__global__ __launch_bounds__(128, 2) void hgemm1t(const __half* __restrict__ A,
                                                  const __half* __restrict__ B,
                                                  const float* __restrict__ bias,
                                                  const float* __restrict__ R,
                                                  float* __restrict__ C,
                                                  __half* __restrict__ Ch,
                                                  int M, int N, int K, int epi) {
    extern __shared__ __half sm16[];

    const int tid  = threadIdx.x;
    const int wid  = tid >> 5;
    const int lane = tid & 31;
    const int bm   = blockIdx.y * 128;
    const int bn   = blockIdx.x * 128;
    const int wm0  = (wid >> 1) * 64;
    const int wn0  = (wid & 1) * 64;

    float acc[4][8][4];
    #pragma unroll
    for (int i = 0; i < 4; i++)
        #pragma unroll
        for (int j = 0; j < 8; j++)
            #pragma unroll
            for (int t = 0; t < 4; t++) acc[i][j][t] = 0.f;

    const int nk = K >> 6;
    const uint32_t smBase = (uint32_t)__cvta_generic_to_shared(sm16);
    #define SADDR(stage, tile, row, col) (smBase + (((stage)*STAGE_H + (tile)*TILE_H + (row)*GSTRIDE + (col)) << 1))

    const __half* gA = A + (size_t)bm * K;
    const __half* gB = B + (size_t)bn * K;

    g_load_stage(smBase, 0, gA, gB, K, 0, tid);
    g_load_stage(smBase, 1, gA, gB, K, 64, tid);

    const int aRow  = (lane & 15);
    const int fBase = ((lane >> 4) << 3);

    int buf = 0, bufw = 2;
    for (int kt = 0; kt < nk; kt++) {
        if (kt + 1 < nk) {
            asm volatile("cp.async.wait_group 1;\n" ::);
        } else {
            asm volatile("cp.async.wait_group 0;\n" ::);
        }
        __syncthreads();
        if (kt + 2 < nk) {
            g_load_stage(smBase, bufw, gA, gB, K, (kt + 2) << 6, tid);
        }

        #pragma unroll
        for (int ks = 0; ks < 4; ks++) {
            const int fcol = ks * 16 + fBase;
            uint32_t bh[4][4];
            #pragma unroll
            for (int nt2 = 0; nt2 < 4; nt2++) {
                LDMX4(bh[nt2][0], bh[nt2][1], bh[nt2][2], bh[nt2][3],
                      SADDR(buf, 1, wn0 + nt2 * 16 + aRow, fcol));
            }
            #pragma unroll
            for (int mt = 0; mt < 4; mt++) {
                uint32_t a0, a1, a2, a3;
                LDMX4(a0, a1, a2, a3, SADDR(buf, 0, wm0 + mt * 16 + aRow, fcol));
                #pragma unroll
                for (int nt = 0; nt < 8; nt++)
                    MMA16816(acc[mt][nt], a0, a1, a2, a3,
                             bh[nt >> 1][nt & 1], bh[nt >> 1][(nt & 1) + 2]);
            }
        }
        buf  = (buf  == NSTAGE - 1) ? 0 : buf + 1;
        bufw = (bufw == NSTAGE - 1) ? 0 : bufw + 1;
    }

    // ---- epilogue ----
    const int g  = lane >> 2;
    const int tg = lane & 3;
    #pragma unroll
    for (int mt = 0; mt < 4; mt++) {
        #pragma unroll
        for (int nt = 0; nt < 8; nt++) {
            const int col = bn + wn0 + nt * 8 + tg * 2;
            const float bx = bias[col], by = bias[col + 1];
            #pragma unroll
            for (int hh = 0; hh < 2; hh++) {
                const int row = bm + wm0 + mt * 16 + g + hh * 8;
                float v0 = acc[mt][nt][hh * 2 + 0] + bx;
                float v1 = acc[mt][nt][hh * 2 + 1] + by;
                if (epi == 4) {
                    v0 = 0.5f * v0 * (1.0f + erff(v0 * 0.7071067811865475f));
                    v1 = 0.5f * v1 * (1.0f + erff(v1 * 0.7071067811865475f));
                }
                if (epi == 2) {
                    const float2 rv = *(const float2*)&R[(size_t)row * N + col];
                    v0 += rv.x; v1 += rv.y;
                    float2 o; o.x = v0; o.y = v1;
                    *(float2*)&C[(size_t)row * N + col] = o;
                } else {
                    if (epi == 3 && col < DMODEL) {   // pre-scale Q for base-2 softmax
                        v0 *= QSCALE; v1 *= QSCALE;
                    }
                    *(__half2*)&Ch[(size_t)row * N + col] = __floats2half2_rn(v0, v1);
                }
            }
        }
    }
}

// ---------------- tensor-core causal flash attention ----------------
// q-tile 128 (8 warps), key chunk 128, double-buffered K/V.
// Q is pre-scaled by 0.125*log2(e); softmax computed in base-2 with ex2.approx.
#define QS 72
#define ATTN_Q_OFF 0
#define ATTN_K_OFF (128 * QS)
#define ATTN_V_OFF (3 * 128 * QS)
#define ATTN_SMEM_BYTES (5 * 128 * QS * 2)   // 92160

__global__ __launch_bounds__(256) void attn_tc(const __half* __restrict__ QKVh,
                                               __half* __restrict__ Oh) {
    extern __shared__ __half asm16[];

    const int bh = blockIdx.y;
    const int b  = bh >> 4;
    const int h  = bh & 15;
    const int q0 = blockIdx.x * 128;
    const int tid  = threadIdx.x;
    const int wq   = tid >> 5;
    const int lane = tid & 31;
    const int g  = lane >> 2;
    const int tg = lane & 3;

    const __half* Qg = QKVh + ((size_t)b * SEQ + q0) * QKVW + h * HDIM;
    const __half* Kg = QKVh + (size_t)b * SEQ * QKVW + DMODEL + h * HDIM;
    const __half* Vg = Kg + DMODEL;

    const uint32_t qB = (uint32_t)__cvta_generic_to_shared(asm16) + ATTN_Q_OFF * 2;
    const uint32_t kB = (uint32_t)__cvta_generic_to_shared(asm16) + ATTN_K_OFF * 2;
    const uint32_t vB = (uint32_t)__cvta_generic_to_shared(asm16) + ATTN_V_OFF * 2;
    const uint32_t bufStride = 128 * QS * 2;

    #pragma unroll
    for (int i = 0; i < 4; i++) {
        int idx = tid + i * 256;
        int r = idx >> 3, sg = (idx & 7) * 8;
        CP16(qB + (r * QS + sg) * 2, Qg + (size_t)r * QKVW + sg);
        CP16(kB + (r * QS + sg) * 2, Kg + (size_t)r * QKVW + sg);
        CP16(vB + (r * QS + sg) * 2, Vg + (size_t)r * QKVW + sg);
    }
    COMMIT();

    uint32_t Qa[4][4];
    float    o[8][4];
    #pragma unroll
    for (int i = 0; i < 8; i++)
        #pragma unroll
        for (int j = 0; j < 4; j++) o[i][j] = 0.f;
    float m0 = -1e30f, m1 = -1e30f, l0 = 0.f, l1 = 0.f;

    const int nchunks = (q0 >> 7) + 1;
    for (int it = 0; it < nchunks; it++) {
        const int buf = it & 1;
        const bool diag = (it == nchunks - 1);
        if (it + 1 < nchunks) {
            const int c1 = (it + 1) << 7;
            #pragma unroll
            for (int i = 0; i < 4; i++) {
                int idx = tid + i * 256;
                int r = idx >> 3, sg = (idx & 7) * 8;
                CP16(kB + (buf ^ 1) * bufStride + (r * QS + sg) * 2, Kg + (size_t)(c1 + r) * QKVW + sg);
                CP16(vB + (buf ^ 1) * bufStride + (r * QS + sg) * 2, Vg + (size_t)(c1 + r) * QKVW + sg);
            }
            COMMIT();
            asm volatile("cp.async.wait_group 1;\n" ::);
        } else {
            asm volatile("cp.async.wait_group 0;\n" ::);
        }
        __syncthreads();

        if (it == 0) {
            #pragma unroll
            for (int kk = 0; kk < 4; kk++) {
                uint32_t addr = qB + ((wq * 16 + (lane & 15)) * QS + kk * 16 + ((lane >> 4) << 3)) * 2;
                LDMX4(Qa[kk][0], Qa[kk][1], Qa[kk][2], Qa[kk][3], addr);
            }
        }

        float s[16][4];
        #pragma unroll
        for (int i = 0; i < 16; i++)
            #pragma unroll
            for (int j = 0; j < 4; j++) s[i][j] = 0.f;

        #pragma unroll
        for (int kk = 0; kk < 4; kk++) {
            #pragma unroll
            for (int nt2 = 0; nt2 < 8; nt2++) {
                if (diag && nt2 > wq) continue;   // fully-masked key block
                uint32_t r0, r1, r2, r3;
                uint32_t addr = kB + buf * bufStride +
                    ((nt2 * 16 + (lane & 15)) * QS + kk * 16 + ((lane >> 4) << 3)) * 2;
                LDMX4(r0, r1, r2, r3, addr);
                MMA16816(s[nt2 * 2],     Qa[kk][0], Qa[kk][1], Qa[kk][2], Qa[kk][3], r0, r2);
                MMA16816(s[nt2 * 2 + 1], Qa[kk][0], Qa[kk][1], Qa[kk][2], Qa[kk][3], r1, r3);
            }
        }

        if (diag) {
            const int row0a = wq * 16 + g;
            const int row1a = row0a + 8;
            #pragma unroll
            for (int nt = 0; nt < 16; nt++) {
                const int key = nt * 8 + 2 * tg;
                if (key     > row0a) s[nt][0] = -1e30f;
                if (key + 1 > row0a) s[nt][1] = -1e30f;
                if (key     > row1a) s[nt][2] = -1e30f;
                if (key + 1 > row1a) s[nt][3] = -1e30f;
            }
        }

        float mx0 = -1e30f, mx1 = -1e30f;
        #pragma unroll
        for (int nt = 0; nt < 16; nt++) {
            mx0 = fmaxf(mx0, fmaxf(s[nt][0], s[nt][1]));
            mx1 = fmaxf(mx1, fmaxf(s[nt][2], s[nt][3]));
        }
        mx0 = fmaxf(mx0, __shfl_xor_sync(0xffffffffu, mx0, 1));
        mx0 = fmaxf(mx0, __shfl_xor_sync(0xffffffffu, mx0, 2));
        mx1 = fmaxf(mx1, __shfl_xor_sync(0xffffffffu, mx1, 1));
        mx1 = fmaxf(mx1, __shfl_xor_sync(0xffffffffu, mx1, 2));
        const float mn0 = fmaxf(m0, mx0), mn1 = fmaxf(m1, mx1);
        const float cr0 = ex2f(m0 - mn0), cr1 = ex2f(m1 - mn1);
        float ps0 = 0.f, ps1 = 0.f;
        #pragma unroll
        for (int nt = 0; nt < 16; nt++) {
            s[nt][0] = ex2f(s[nt][0] - mn0);
            s[nt][1] = ex2f(s[nt][1] - mn0);
            s[nt][2] = ex2f(s[nt][2] - mn1);
            s[nt][3] = ex2f(s[nt][3] - mn1);
            ps0 += s[nt][0] + s[nt][1];
            ps1 += s[nt][2] + s[nt][3];
        }
        ps0 += __shfl_xor_sync(0xffffffffu, ps0, 1);
        ps0 += __shfl_xor_sync(0xffffffffu, ps0, 2);
        ps1 += __shfl_xor_sync(0xffffffffu, ps1, 1);
        ps1 += __shfl_xor_sync(0xffffffffu, ps1, 2);
        l0 = l0 * cr0 + ps0;
        l1 = l1 * cr1 + ps1;
        m0 = mn0; m1 = mn1;
        #pragma unroll
        for (int nd = 0; nd < 8; nd++) {
            o[nd][0] *= cr0; o[nd][1] *= cr0;
            o[nd][2] *= cr1; o[nd][3] *= cr1;
        }

        #pragma unroll
        for (int kk = 0; kk < 8; kk++) {
            if (diag && kk > wq) continue;        // P is exactly 0 there
            __half2 t0 = __floats2half2_rn(s[2*kk][0],   s[2*kk][1]);
            __half2 t1 = __floats2half2_rn(s[2*kk][2],   s[2*kk][3]);
            __half2 t2 = __floats2half2_rn(s[2*kk+1][0], s[2*kk+1][1]);
            __half2 t3 = __floats2half2_rn(s[2*kk+1][2], s[2*kk+1][3]);
            uint32_t pa0 = *(uint32_t*)&t0, pa1 = *(uint32_t*)&t1;
            uint32_t pa2 = *(uint32_t*)&t2, pa3 = *(uint32_t*)&t3;
            #pragma unroll
            for (int nd2 = 0; nd2 < 4; nd2++) {
                uint32_t r0, r1, r2, r3;
                uint32_t addr = vB + buf * bufStride +
                    ((kk * 16 + (lane & 15)) * QS + nd2 * 16 + ((lane >> 4) << 3)) * 2;
                LDMX4T(r0, r1, r2, r3, addr);
                MMA16816(o[nd2 * 2],     pa0, pa1, pa2, pa3, r0, r1);
                MMA16816(o[nd2 * 2 + 1], pa0, pa1, pa2, pa3, r2, r3);
            }
        }
        __syncthreads();
    }

    const float inv0 = 1.f / l0, inv1 = 1.f / l1;
    const int row0 = q0 + wq * 16 + g;
    const size_t ob0 = ((size_t)b * SEQ + row0) * DMODEL + h * HDIM;
    const size_t ob1 = ob0 + 8 * DMODEL;
    #pragma unroll
    for (int nd = 0; nd < 8; nd++) {
        const int d = nd * 8 + 2 * tg;
        *(__half2*)&Oh[ob0 + d] = __floats2half2_rn(o[nd][0] * inv0, o[nd][1] * inv0);
        *(__half2*)&Oh[ob1 + d] = __floats2half2_rn(o[nd][2] * inv1, o[nd][3] * inv1);
    }
}

// ---------------- launcher ----------------
extern "C" void kernel_launch(void* const* d_in, const int* in_sizes, int n_in,
                              void* d_out, int out_size) {
    const float* x     = (const float*)d_in[0];
    const float* Wq    = (const float*)d_in[2];
    const float* bq    = (const float*)d_in[3];
    const float* Wk    = (const float*)d_in[4];
    const float* bk    = (const float*)d_in[5];
    const float* Wv    = (const float*)d_in[6];
    const float* bv    = (const float*)d_in[7];
    const float* Wo    = (const float*)d_in[8];
    const float* bo    = (const float*)d_in[9];
    const float* W1    = (const float*)d_in[10];
    const float* b1    = (const float*)d_in[11];
    const float* W2    = (const float*)d_in[12];
    const float* b2    = (const float*)d_in[13];
    const float* g1    = (const float*)d_in[14];
    const float* beta1 = (const float*)d_in[15];
    const float* g2    = (const float*)d_in[16];
    const float* beta2 = (const float*)d_in[17];
    float* out = (float*)d_out;

    float *x2, *bqkv;
    __half *qkvh, *ah, *hh, *wh;
    cudaGetSymbolAddress((void**)&x2,   g_x2);
    cudaGetSymbolAddress((void**)&bqkv, g_bqkv);
    cudaGetSymbolAddress((void**)&qkvh, g_qkvh);
    cudaGetSymbolAddress((void**)&ah,   g_ah);
    cudaGetSymbolAddress((void**)&hh,   g_hh);
    cudaGetSymbolAddress((void**)&wh,   g_wh);

    static cudaStream_t s2 = nullptr;
    static cudaEvent_t eF, e1, e2, e3, e4;
    static bool init_done = false;
    if (!init_done) {
        cudaFuncSetAttribute(hgemm1t, cudaFuncAttributeMaxDynamicSharedMemorySize, GSMEM_BYTES);
        cudaFuncSetAttribute(attn_tc, cudaFuncAttributeMaxDynamicSharedMemorySize, ATTN_SMEM_BYTES);
        cudaStreamCreateWithFlags(&s2, cudaStreamNonBlocking);
        cudaEventCreateWithFlags(&eF, cudaEventDisableTiming);
        cudaEventCreateWithFlags(&e1, cudaEventDisableTiming);
        cudaEventCreateWithFlags(&e2, cudaEventDisableTiming);
        cudaEventCreateWithFlags(&e3, cudaEventDisableTiming);
        cudaEventCreateWithFlags(&e4, cudaEventDisableTiming);
        init_done = true;
    }

    const int M = MROWS, D = DMODEL, F = FFDIM;
    const size_t DD = (size_t)D * D;
    __half* wqkv = wh;
    __half* wo16 = wh + 3 * DD;
    __half* w116 = wh + 4 * DD;
    __half* w216 = wh + 8 * DD;

    // ---- fork side stream for weight conversions ----
    cudaEventRecord(eF, 0);
    cudaStreamWaitEvent(s2, eF, 0);
    cvt16<<<(int)(DD / 8) / 256, 256, 0, s2>>>(Wq, wqkv);
    cvt16<<<(int)(DD / 8) / 256, 256, 0, s2>>>(Wk, wqkv + DD);
    cvt16<<<(int)(DD / 8) / 256, 256, 0, s2>>>(Wv, wqkv + 2 * DD);
    pack_bias<<<QKVW / 256, 256, 0, s2>>>(bq, bk, bv, bqkv);
    cudaEventRecord(e1, s2);
    cvt16<<<(int)(DD / 8) / 256, 256, 0, s2>>>(Wo, wo16);
    cudaEventRecord(e2, s2);
    cvt16<<<(int)((size_t)F * D / 8) / 256, 256, 0, s2>>>(W1, w116);
    cudaEventRecord(e3, s2);
    cvt16<<<(int)((size_t)D * F / 8) / 256, 256, 0, s2>>>(W2, w216);
    cudaEventRecord(e4, s2);

    // ---- main stream ----
    ln_h16<<<M, 256>>>(x, g1, beta1, ah);

    cudaStreamWaitEvent(0, e1, 0);
    dim3 gQKV(QKVW / 128, M / 128);
    hgemm1t<<<gQKV, 128, GSMEM_BYTES>>>(ah, wqkv, bqkv, nullptr,
                                        nullptr, qkvh, M, QKVW, D, 3);

    dim3 gA(SEQ / 128, BSZ * NHEADS);
    attn_tc<<<gA, 256, ATTN_SMEM_BYTES>>>(qkvh, ah);

    cudaStreamWaitEvent(0, e2, 0);
    dim3 gD(D / 128, M / 128);
    hgemm1t<<<gD, 128, GSMEM_BYTES>>>(ah, wo16, bo, x,
                                      x2, nullptr, M, D, D, 2);

    ln_h16<<<M, 256>>>(x2, g2, beta2, ah);

    cudaStreamWaitEvent(0, e3, 0);
    dim3 gF1(F / 128, M / 128);
    hgemm1t<<<gF1, 128, GSMEM_BYTES>>>(ah, w116, b1, nullptr,
                                       nullptr, hh, M, F, D, 4);

    cudaStreamWaitEvent(0, e4, 0);
    hgemm1t<<<gD, 128, GSMEM_BYTES>>>(hh, w216, b2, x2,
                                      out, nullptr, M, D, F, 2);
}

// round 12
// speedup vs baseline: 1.0074x; 1.0074x over previous
#include <cuda_runtime.h>
#include <cuda_fp16.h>
#include <math.h>
#include <stdint.h>

// ---------------- problem constants ----------------
#define BSZ    2
#define SEQ    2048
#define DMODEL 1024
#define NHEADS 16
#define HDIM   64
#define FFDIM  4096
#define MROWS (BSZ*SEQ)          // 4096
#define QKVW  (3*DMODEL)         // 3072
#define LN_EPS 1e-5f
#define QSCALE 0.18033688011112042f   // 0.125 * log2(e)

// ---------------- scratch (device globals; no allocs) ----------------
__device__ float  g_x2  [MROWS*DMODEL];
__device__ float  g_bqkv[QKVW];
__device__ __half g_qkvh[(size_t)MROWS*QKVW];
__device__ __half g_ah[(size_t)MROWS*DMODEL];        // activations (fp16)
__device__ __half g_hh[(size_t)MROWS*FFDIM];         // FFN hidden (fp16)
__device__ __half g_wh[(size_t)12*1024*1024];        // all weights fp16 (24MB)

// ---------------- LayerNorm -> fp16 directly ----------------
__global__ __launch_bounds__(256) void ln_h16(const float* __restrict__ x,
                                              const float* __restrict__ g,
                                              const float* __restrict__ b,
                                              __half* __restrict__ ah) {
    int row = blockIdx.x;
    int t   = threadIdx.x;
    const float4 v = ((const float4*)(x + (size_t)row * DMODEL))[t];
    float s  = v.x + v.y + v.z + v.w;
    float ss = v.x*v.x + v.y*v.y + v.z*v.z + v.w*v.w;
    #pragma unroll
    for (int o = 16; o; o >>= 1) {
        s  += __shfl_xor_sync(0xffffffffu, s,  o);
        ss += __shfl_xor_sync(0xffffffffu, ss, o);
    }
    __shared__ float rs[8], rss[8];
    if ((t & 31) == 0) { rs[t >> 5] = s; rss[t >> 5] = ss; }
    __syncthreads();
    float S = 0.f, SS = 0.f;
    #pragma unroll
    for (int i = 0; i < 8; i++) { S += rs[i]; SS += rss[i]; }
    float mean = S * (1.f / DMODEL);
    float var  = SS * (1.f / DMODEL) - mean * mean;
    float rstd = rsqrtf(var + LN_EPS);
    const float4 gv = ((const float4*)g)[t];
    const float4 bv = ((const float4*)b)[t];
    float o0 = (v.x - mean) * rstd * gv.x + bv.x;
    float o1 = (v.y - mean) * rstd * gv.y + bv.y;
    float o2 = (v.z - mean) * rstd * gv.z + bv.z;
    float o3 = (v.w - mean) * rstd * gv.w + bv.w;
    __half2* ph = (__half2*)(ah + (size_t)row * DMODEL);
    ph[t*2]   = __floats2half2_rn(o0, o1);
    ph[t*2+1] = __floats2half2_rn(o2, o3);
}

// ---------------- fp32 -> fp16 convert (weights), 8 elems/thread ----------------
__global__ __launch_bounds__(256) void cvt16(const float* __restrict__ src,
                                             __half* __restrict__ dst) {
    size_t i = ((size_t)blockIdx.x * 256 + threadIdx.x) * 8;
    const float4 f0 = *(const float4*)(src + i);
    const float4 f1 = *(const float4*)(src + i + 4);
    __half2 h0 = __floats2half2_rn(f0.x, f0.y);
    __half2 h1 = __floats2half2_rn(f0.z, f0.w);
    __half2 h2 = __floats2half2_rn(f1.x, f1.y);
    __half2 h3 = __floats2half2_rn(f1.z, f1.w);
    uint4 ph;
    ph.x = *(uint32_t*)&h0; ph.y = *(uint32_t*)&h1;
    ph.z = *(uint32_t*)&h2; ph.w = *(uint32_t*)&h3;
    *(uint4*)(dst + i) = ph;
}

__global__ void pack_bias(const float* __restrict__ a, const float* __restrict__ b,
                          const float* __restrict__ c, float* __restrict__ out) {
    int i = blockIdx.x * 256 + threadIdx.x;
    float v = (i < 1024) ? a[i] : (i < 2048) ? b[i - 1024] : c[i - 2048];
    out[i] = v;
}

// ---------------- PTX helpers ----------------
#define CP16(sa, ga) asm volatile("cp.async.cg.shared.global [%0], [%1], 16;\n" :: "r"(sa), "l"(ga))
#define COMMIT() asm volatile("cp.async.commit_group;\n" ::)
#define LDMX4(r0,r1,r2,r3,addr) asm volatile( \
    "ldmatrix.sync.aligned.m8n8.x4.shared.b16 {%0,%1,%2,%3}, [%4];" \
    : "=r"(r0), "=r"(r1), "=r"(r2), "=r"(r3) : "r"(addr))
#define LDMX4T(r0,r1,r2,r3,addr) asm volatile( \
    "ldmatrix.sync.aligned.m8n8.x4.trans.shared.b16 {%0,%1,%2,%3}, [%4];" \
    : "=r"(r0), "=r"(r1), "=r"(r2), "=r"(r3) : "r"(addr))
#define MMA16816(d, a0,a1,a2,a3, b0,b1) asm volatile( \
    "mma.sync.aligned.m16n8k16.row.col.f32.f16.f16.f32 " \
    "{%0,%1,%2,%3}, {%4,%5,%6,%7}, {%8,%9}, {%0,%1,%2,%3};" \
    : "+f"(d[0]), "+f"(d[1]), "+f"(d[2]), "+f"(d[3]) \
    : "r"(a0), "r"(a1), "r"(a2), "r"(a3), "r"(b0), "r"(b1))

__device__ __forceinline__ float ex2f(float x) {
    float y;
    asm("ex2.approx.f32 %0, %1;" : "=f"(y) : "f"(x));
    return y;
}

// ---------------- single-term fp16 GEMM (BK=64, warp tile 64x64, 2-stage) ----------------
#define GSTRIDE 72
#define TILE_H  (128 * GSTRIDE)
#define STAGE_H (2 * TILE_H)
#define GSMEM_BYTES (2 * STAGE_H * 2)   // 73728 -> 2 CTAs/SM

__device__ __forceinline__ void g_load_stage(uint32_t smBase, int stg,
                                             const __half* gA, const __half* gB,
                                             int K, int k0, int tid) {
    const uint32_t sb = smBase + (uint32_t)(stg * STAGE_H * 2);
    #pragma unroll
    for (int i = 0; i < 8; i++) {
        const int idx = tid + i * 128;          // [0,1024)
        const int r = idx >> 3, sg = (idx & 7) * 8;
        const uint32_t so = (uint32_t)((r * GSTRIDE + sg) << 1);
        const size_t go = (size_t)r * K + k0 + sg;
        CP16(sb + so,              gA + go);
        CP16(sb + TILE_H * 2 + so, gB + go);
    }
    COMMIT();
}

// epi: 2 = bias+residual -> float C ; 3 = bias (+Q-scale for col<1024) -> half Ch ;
//      4 = bias+GELU -> half Ch
__global__ __launch_bounds__(128, 2) void hgemm1t(const __half* __restrict__ A,
                                                  const __half* __restrict__ B,
                                                  const float* __restrict__ bias,
                                                  const float* __restrict__ R,
                                                  float* __restrict__ C,
                                                  __half* __restrict__ Ch,
                                                  int M, int N, int K, int epi) {
    extern __shared__ __half sm16[];

    const int tid  = threadIdx.x;
    const int wid  = tid >> 5;
    const int lane = tid & 31;
    const int bm   = blockIdx.y * 128;
    const int bn   = blockIdx.x * 128;
    const int wm0  = (wid >> 1) * 64;   // 2x2 warp grid, 64x64 each
    const int wn0  = (wid & 1) * 64;

    float acc[4][8][4];
    #pragma unroll
    for (int i = 0; i < 4; i++)
        #pragma unroll
        for (int j = 0; j < 8; j++)
            #pragma unroll
            for (int t = 0; t < 4; t++) acc[i][j][t] = 0.f;

    const int nk = K >> 6;
    const uint32_t smBase = (uint32_t)__cvta_generic_to_shared(sm16);
    #define SADDR(stage, tile, row, col) (smBase + (((stage)*STAGE_H + (tile)*TILE_H + (row)*GSTRIDE + (col)) << 1))

    const __half* gA = A + (size_t)bm * K;
    const __half* gB = B + (size_t)bn * K;

    g_load_stage(smBase, 0, gA, gB, K, 0, tid);

    const int aRow  = (lane & 15);
    const int fBase = ((lane >> 4) << 3);

    for (int kt = 0; kt < nk; kt++) {
        const int buf = kt & 1;
        asm volatile("cp.async.wait_group 0;\n" ::);
        __syncthreads();
        if (kt + 1 < nk)
            g_load_stage(smBase, buf ^ 1, gA, gB, K, (kt + 1) << 6, tid);

        #pragma unroll
        for (int ks = 0; ks < 4; ks++) {
            const int fcol = ks * 16 + fBase;
            uint32_t bh[4][4];
            #pragma unroll
            for (int nt2 = 0; nt2 < 4; nt2++) {
                LDMX4(bh[nt2][0], bh[nt2][1], bh[nt2][2], bh[nt2][3],
                      SADDR(buf, 1, wn0 + nt2 * 16 + aRow, fcol));
            }
            #pragma unroll
            for (int mt = 0; mt < 4; mt++) {
                uint32_t a0, a1, a2, a3;
                LDMX4(a0, a1, a2, a3, SADDR(buf, 0, wm0 + mt * 16 + aRow, fcol));
                #pragma unroll
                for (int nt = 0; nt < 8; nt++)
                    MMA16816(acc[mt][nt], a0, a1, a2, a3,
                             bh[nt >> 1][nt & 1], bh[nt >> 1][(nt & 1) + 2]);
            }
        }
    }

    // ---- epilogue ----
    const int g  = lane >> 2;
    const int tg = lane & 3;
    #pragma unroll
    for (int mt = 0; mt < 4; mt++) {
        #pragma unroll
        for (int nt = 0; nt < 8; nt++) {
            const int col = bn + wn0 + nt * 8 + tg * 2;
            const float bx = bias[col], by = bias[col + 1];
            #pragma unroll
            for (int hh = 0; hh < 2; hh++) {
                const int row = bm + wm0 + mt * 16 + g + hh * 8;
                float v0 = acc[mt][nt][hh * 2 + 0] + bx;
                float v1 = acc[mt][nt][hh * 2 + 1] + by;
                if (epi == 4) {
                    v0 = 0.5f * v0 * (1.0f + erff(v0 * 0.7071067811865475f));
                    v1 = 0.5f * v1 * (1.0f + erff(v1 * 0.7071067811865475f));
                }
                if (epi == 2) {
                    const float2 rv = *(const float2*)&R[(size_t)row * N + col];
                    v0 += rv.x; v1 += rv.y;
                    float2 o; o.x = v0; o.y = v1;
                    *(float2*)&C[(size_t)row * N + col] = o;
                } else {
                    if (epi == 3 && col < DMODEL) {   // pre-scale Q for base-2 softmax
                        v0 *= QSCALE; v1 *= QSCALE;
                    }
                    *(__half2*)&Ch[(size_t)row * N + col] = __floats2half2_rn(v0, v1);
                }
            }
        }
    }
}

// ---------------- tensor-core causal flash attention ----------------
// q-tile 128 (8 warps), key chunk 128, double-buffered K/V.
// Q pre-scaled by 0.125*log2(e); base-2 softmax via ex2.approx; masked blocks skipped.
#define QS 72
#define ATTN_Q_OFF 0
#define ATTN_K_OFF (128 * QS)
#define ATTN_V_OFF (3 * 128 * QS)
#define ATTN_SMEM_BYTES (5 * 128 * QS * 2)   // 92160

__global__ __launch_bounds__(256) void attn_tc(const __half* __restrict__ QKVh,
                                               __half* __restrict__ Oh) {
    extern __shared__ __half asm16[];

    const int bh = blockIdx.y;
    const int b  = bh >> 4;
    const int h  = bh & 15;
    const int q0 = blockIdx.x * 128;
    const int tid  = threadIdx.x;
    const int wq   = tid >> 5;
    const int lane = tid & 31;
    const int g  = lane >> 2;
    const int tg = lane & 3;

    const __half* Qg = QKVh + ((size_t)b * SEQ + q0) * QKVW + h * HDIM;
    const __half* Kg = QKVh + (size_t)b * SEQ * QKVW + DMODEL + h * HDIM;
    const __half* Vg = Kg + DMODEL;

    const uint32_t qB = (uint32_t)__cvta_generic_to_shared(asm16) + ATTN_Q_OFF * 2;
    const uint32_t kB = (uint32_t)__cvta_generic_to_shared(asm16) + ATTN_K_OFF * 2;
    const uint32_t vB = (uint32_t)__cvta_generic_to_shared(asm16) + ATTN_V_OFF * 2;
    const uint32_t bufStride = 128 * QS * 2;

    #pragma unroll
    for (int i = 0; i < 4; i++) {
        int idx = tid + i * 256;
        int r = idx >> 3, sg = (idx & 7) * 8;
        CP16(qB + (r * QS + sg) * 2, Qg + (size_t)r * QKVW + sg);
        CP16(kB + (r * QS + sg) * 2, Kg + (size_t)r * QKVW + sg);
        CP16(vB + (r * QS + sg) * 2, Vg + (size_t)r * QKVW + sg);
    }
    COMMIT();

    uint32_t Qa[4][4];
    float    o[8][4];
    #pragma unroll
    for (int i = 0; i < 8; i++)
        #pragma unroll
        for (int j = 0; j < 4; j++) o[i][j] = 0.f;
    float m0 = -1e30f, m1 = -1e30f, l0 = 0.f, l1 = 0.f;

    const int nchunks = (q0 >> 7) + 1;
    for (int it = 0; it < nchunks; it++) {
        const int buf = it & 1;
        const bool diag = (it == nchunks - 1);
        if (it + 1 < nchunks) {
            const int c1 = (it + 1) << 7;
            #pragma unroll
            for (int i = 0; i < 4; i++) {
                int idx = tid + i * 256;
                int r = idx >> 3, sg = (idx & 7) * 8;
                CP16(kB + (buf ^ 1) * bufStride + (r * QS + sg) * 2, Kg + (size_t)(c1 + r) * QKVW + sg);
                CP16(vB + (buf ^ 1) * bufStride + (r * QS + sg) * 2, Vg + (size_t)(c1 + r) * QKVW + sg);
            }
            COMMIT();
            asm volatile("cp.async.wait_group 1;\n" ::);
        } else {
            asm volatile("cp.async.wait_group 0;\n" ::);
        }
        __syncthreads();

        if (it == 0) {
            #pragma unroll
            for (int kk = 0; kk < 4; kk++) {
                uint32_t addr = qB + ((wq * 16 + (lane & 15)) * QS + kk * 16 + ((lane >> 4) << 3)) * 2;
                LDMX4(Qa[kk][0], Qa[kk][1], Qa[kk][2], Qa[kk][3], addr);
            }
        }

        float s[16][4];
        #pragma unroll
        for (int i = 0; i < 16; i++)
            #pragma unroll
            for (int j = 0; j < 4; j++) s[i][j] = 0.f;

        #pragma unroll
        for (int kk = 0; kk < 4; kk++) {
            #pragma unroll
            for (int nt2 = 0; nt2 < 8; nt2++) {
                if (diag && nt2 > wq) continue;   // fully-masked key block
                uint32_t r0, r1, r2, r3;
                uint32_t addr = kB + buf * bufStride +
                    ((nt2 * 16 + (lane & 15)) * QS + kk * 16 + ((lane >> 4) << 3)) * 2;
                LDMX4(r0, r1, r2, r3, addr);
                MMA16816(s[nt2 * 2],     Qa[kk][0], Qa[kk][1], Qa[kk][2], Qa[kk][3], r0, r2);
                MMA16816(s[nt2 * 2 + 1], Qa[kk][0], Qa[kk][1], Qa[kk][2], Qa[kk][3], r1, r3);
            }
        }

        if (diag) {
            const int row0a = wq * 16 + g;
            const int row1a = row0a + 8;
            #pragma unroll
            for (int nt = 0; nt < 16; nt++) {
                const int key = nt * 8 + 2 * tg;
                if (key     > row0a) s[nt][0] = -1e30f;
                if (key + 1 > row0a) s[nt][1] = -1e30f;
                if (key     > row1a) s[nt][2] = -1e30f;
                if (key + 1 > row1a) s[nt][3] = -1e30f;
            }
        }

        float mx0 = -1e30f, mx1 = -1e30f;
        #pragma unroll
        for (int nt = 0; nt < 16; nt++) {
            mx0 = fmaxf(mx0, fmaxf(s[nt][0], s[nt][1]));
            mx1 = fmaxf(mx1, fmaxf(s[nt][2], s[nt][3]));
        }
        mx0 = fmaxf(mx0, __shfl_xor_sync(0xffffffffu, mx0, 1));
        mx0 = fmaxf(mx0, __shfl_xor_sync(0xffffffffu, mx0, 2));
        mx1 = fmaxf(mx1, __shfl_xor_sync(0xffffffffu, mx1, 1));
        mx1 = fmaxf(mx1, __shfl_xor_sync(0xffffffffu, mx1, 2));
        const float mn0 = fmaxf(m0, mx0), mn1 = fmaxf(m1, mx1);
        const float cr0 = ex2f(m0 - mn0), cr1 = ex2f(m1 - mn1);
        float ps0 = 0.f, ps1 = 0.f;
        #pragma unroll
        for (int nt = 0; nt < 16; nt++) {
            s[nt][0] = ex2f(s[nt][0] - mn0);
            s[nt][1] = ex2f(s[nt][1] - mn0);
            s[nt][2] = ex2f(s[nt][2] - mn1);
            s[nt][3] = ex2f(s[nt][3] - mn1);
            ps0 += s[nt][0] + s[nt][1];
            ps1 += s[nt][2] + s[nt][3];
        }
        ps0 += __shfl_xor_sync(0xffffffffu, ps0, 1);
        ps0 += __shfl_xor_sync(0xffffffffu, ps0, 2);
        ps1 += __shfl_xor_sync(0xffffffffu, ps1, 1);
        ps1 += __shfl_xor_sync(0xffffffffu, ps1, 2);
        l0 = l0 * cr0 + ps0;
        l1 = l1 * cr1 + ps1;
        m0 = mn0; m1 = mn1;
        #pragma unroll
        for (int nd = 0; nd < 8; nd++) {
            o[nd][0] *= cr0; o[nd][1] *= cr0;
            o[nd][2] *= cr1; o[nd][3] *= cr1;
        }

        #pragma unroll
        for (int kk = 0; kk < 8; kk++) {
            if (diag && kk > wq) continue;        // P is exactly 0 there
            __half2 t0 = __floats2half2_rn(s[2*kk][0],   s[2*kk][1]);
            __half2 t1 = __floats2half2_rn(s[2*kk][2],   s[2*kk][3]);
            __half2 t2 = __floats2half2_rn(s[2*kk+1][0], s[2*kk+1][1]);
            __half2 t3 = __floats2half2_rn(s[2*kk+1][2], s[2*kk+1][3]);
            uint32_t pa0 = *(uint32_t*)&t0, pa1 = *(uint32_t*)&t1;
            uint32_t pa2 = *(uint32_t*)&t2, pa3 = *(uint32_t*)&t3;
            #pragma unroll
            for (int nd2 = 0; nd2 < 4; nd2++) {
                uint32_t r0, r1, r2, r3;
                uint32_t addr = vB + buf * bufStride +
                    ((kk * 16 + (lane & 15)) * QS + nd2 * 16 + ((lane >> 4) << 3)) * 2;
                LDMX4T(r0, r1, r2, r3, addr);
                MMA16816(o[nd2 * 2],     pa0, pa1, pa2, pa3, r0, r1);
                MMA16816(o[nd2 * 2 + 1], pa0, pa1, pa2, pa3, r2, r3);
            }
        }
        __syncthreads();
    }

    const float inv0 = 1.f / l0, inv1 = 1.f / l1;
    const int row0 = q0 + wq * 16 + g;
    const size_t ob0 = ((size_t)b * SEQ + row0) * DMODEL + h * HDIM;
    const size_t ob1 = ob0 + 8 * DMODEL;
    #pragma unroll
    for (int nd = 0; nd < 8; nd++) {
        const int d = nd * 8 + 2 * tg;
        *(__half2*)&Oh[ob0 + d] = __floats2half2_rn(o[nd][0] * inv0, o[nd][1] * inv0);
        *(__half2*)&Oh[ob1 + d] = __floats2half2_rn(o[nd][2] * inv1, o[nd][3] * inv1);
    }
}

// ---------------- launcher ----------------
extern "C" void kernel_launch(void* const* d_in, const int* in_sizes, int n_in,
                              void* d_out, int out_size) {
    const float* x     = (const float*)d_in[0];
    const float* Wq    = (const float*)d_in[2];
    const float* bq    = (const float*)d_in[3];
    const float* Wk    = (const float*)d_in[4];
    const float* bk    = (const float*)d_in[5];
    const float* Wv    = (const float*)d_in[6];
    const float* bv    = (const float*)d_in[7];
    const float* Wo    = (const float*)d_in[8];
    const float* bo    = (const float*)d_in[9];
    const float* W1    = (const float*)d_in[10];
    const float* b1    = (const float*)d_in[11];
    const float* W2    = (const float*)d_in[12];
    const float* b2    = (const float*)d_in[13];
    const float* g1    = (const float*)d_in[14];
    const float* beta1 = (const float*)d_in[15];
    const float* g2    = (const float*)d_in[16];
    const float* beta2 = (const float*)d_in[17];
    float* out = (float*)d_out;

    float *x2, *bqkv;
    __half *qkvh, *ah, *hh, *wh;
    cudaGetSymbolAddress((void**)&x2,   g_x2);
    cudaGetSymbolAddress((void**)&bqkv, g_bqkv);
    cudaGetSymbolAddress((void**)&qkvh, g_qkvh);
    cudaGetSymbolAddress((void**)&ah,   g_ah);
    cudaGetSymbolAddress((void**)&hh,   g_hh);
    cudaGetSymbolAddress((void**)&wh,   g_wh);

    static cudaStream_t s2 = nullptr;
    static cudaEvent_t eF, e1, e2, e3, e4;
    static bool init_done = false;
    if (!init_done) {
        cudaFuncSetAttribute(hgemm1t, cudaFuncAttributeMaxDynamicSharedMemorySize, GSMEM_BYTES);
        cudaFuncSetAttribute(attn_tc, cudaFuncAttributeMaxDynamicSharedMemorySize, ATTN_SMEM_BYTES);
        cudaStreamCreateWithFlags(&s2, cudaStreamNonBlocking);
        cudaEventCreateWithFlags(&eF, cudaEventDisableTiming);
        cudaEventCreateWithFlags(&e1, cudaEventDisableTiming);
        cudaEventCreateWithFlags(&e2, cudaEventDisableTiming);
        cudaEventCreateWithFlags(&e3, cudaEventDisableTiming);
        cudaEventCreateWithFlags(&e4, cudaEventDisableTiming);
        init_done = true;
    }

    const int M = MROWS, D = DMODEL, F = FFDIM;
    const size_t DD = (size_t)D * D;
    __half* wqkv = wh;
    __half* wo16 = wh + 3 * DD;
    __half* w116 = wh + 4 * DD;
    __half* w216 = wh + 8 * DD;

    // ---- fork side stream for weight conversions ----
    cudaEventRecord(eF, 0);
    cudaStreamWaitEvent(s2, eF, 0);
    cvt16<<<(int)(DD / 8) / 256, 256, 0, s2>>>(Wq, wqkv);
    cvt16<<<(int)(DD / 8) / 256, 256, 0, s2>>>(Wk, wqkv + DD);
    cvt16<<<(int)(DD / 8) / 256, 256, 0, s2>>>(Wv, wqkv + 2 * DD);
    pack_bias<<<QKVW / 256, 256, 0, s2>>>(bq, bk, bv, bqkv);
    cudaEventRecord(e1, s2);
    cvt16<<<(int)(DD / 8) / 256, 256, 0, s2>>>(Wo, wo16);
    cudaEventRecord(e2, s2);
    cvt16<<<(int)((size_t)F * D / 8) / 256, 256, 0, s2>>>(W1, w116);
    cudaEventRecord(e3, s2);
    cvt16<<<(int)((size_t)D * F / 8) / 256, 256, 0, s2>>>(W2, w216);
    cudaEventRecord(e4, s2);

    // ---- main stream ----
    ln_h16<<<M, 256>>>(x, g1, beta1, ah);

    cudaStreamWaitEvent(0, e1, 0);
    dim3 gQKV(QKVW / 128, M / 128);
    hgemm1t<<<gQKV, 128, GSMEM_BYTES>>>(ah, wqkv, bqkv, nullptr,
                                        nullptr, qkvh, M, QKVW, D, 3);

    dim3 gA(SEQ / 128, BSZ * NHEADS);
    attn_tc<<<gA, 256, ATTN_SMEM_BYTES>>>(qkvh, ah);

    cudaStreamWaitEvent(0, e2, 0);
    dim3 gD(D / 128, M / 128);
    hgemm1t<<<gD, 128, GSMEM_BYTES>>>(ah, wo16, bo, x,
                                      x2, nullptr, M, D, D, 2);

    ln_h16<<<M, 256>>>(x2, g2, beta2, ah);

    cudaStreamWaitEvent(0, e3, 0);
    dim3 gF1(F / 128, M / 128);
    hgemm1t<<<gF1, 128, GSMEM_BYTES>>>(ah, w116, b1, nullptr,
                                       nullptr, hh, M, F, D, 4);

    cudaStreamWaitEvent(0, e4, 0);
    hgemm1t<<<gD, 128, GSMEM_BYTES>>>(hh, w216, b2, x2,
                                      out, nullptr, M, D, F, 2);
}

// round 13
// speedup vs baseline: 1.1706x; 1.1620x over previous
#include <cuda_runtime.h>
#include <cuda_fp16.h>
#include <math.h>
#include <stdint.h>

// ---------------- problem constants ----------------
#define BSZ    2
#define SEQ    2048
#define DMODEL 1024
#define NHEADS 16
#define HDIM   64
#define FFDIM  4096
#define MROWS (BSZ*SEQ)          // 4096
#define QKVW  (3*DMODEL)         // 3072
#define LN_EPS 1e-5f

// ---------------- scratch (device globals; no allocs) ----------------
__device__ float  g_x2  [MROWS*DMODEL];
__device__ float  g_bqkv[QKVW];
__device__ __half g_qkvh[(size_t)MROWS*QKVW];
__device__ __half g_ah[(size_t)MROWS*DMODEL];        // activations (fp16)
__device__ __half g_hh[(size_t)MROWS*FFDIM];         // FFN hidden (fp16)
__device__ __half g_wh[(size_t)12*1024*1024];        // all weights fp16 (24MB)

// ---------------- LayerNorm -> fp16 directly ----------------
__global__ __launch_bounds__(256) void ln_h16(const float* __restrict__ x,
                                              const float* __restrict__ g,
                                              const float* __restrict__ b,
                                              __half* __restrict__ ah) {
    int row = blockIdx.x;
    int t   = threadIdx.x;
    const float4 v = ((const float4*)(x + (size_t)row * DMODEL))[t];
    float s  = v.x + v.y + v.z + v.w;
    float ss = v.x*v.x + v.y*v.y + v.z*v.z + v.w*v.w;
    #pragma unroll
    for (int o = 16; o; o >>= 1) {
        s  += __shfl_xor_sync(0xffffffffu, s,  o);
        ss += __shfl_xor_sync(0xffffffffu, ss, o);
    }
    __shared__ float rs[8], rss[8];
    if ((t & 31) == 0) { rs[t >> 5] = s; rss[t >> 5] = ss; }
    __syncthreads();
    float S = 0.f, SS = 0.f;
    #pragma unroll
    for (int i = 0; i < 8; i++) { S += rs[i]; SS += rss[i]; }
    float mean = S * (1.f / DMODEL);
    float var  = SS * (1.f / DMODEL) - mean * mean;
    float rstd = rsqrtf(var + LN_EPS);
    const float4 gv = ((const float4*)g)[t];
    const float4 bv = ((const float4*)b)[t];
    float o0 = (v.x - mean) * rstd * gv.x + bv.x;
    float o1 = (v.y - mean) * rstd * gv.y + bv.y;
    float o2 = (v.z - mean) * rstd * gv.z + bv.z;
    float o3 = (v.w - mean) * rstd * gv.w + bv.w;
    __half2* ph = (__half2*)(ah + (size_t)row * DMODEL);
    ph[t*2]   = __floats2half2_rn(o0, o1);
    ph[t*2+1] = __floats2half2_rn(o2, o3);
}

// ---------------- fp32 -> fp16 convert (weights), 8 elems/thread ----------------
__global__ __launch_bounds__(256) void cvt16(const float* __restrict__ src,
                                             __half* __restrict__ dst) {
    size_t i = ((size_t)blockIdx.x * 256 + threadIdx.x) * 8;
    const float4 f0 = *(const float4*)(src + i);
    const float4 f1 = *(const float4*)(src + i + 4);
    __half2 h0 = __floats2half2_rn(f0.x, f0.y);
    __half2 h1 = __floats2half2_rn(f0.z, f0.w);
    __half2 h2 = __floats2half2_rn(f1.x, f1.y);
    __half2 h3 = __floats2half2_rn(f1.z, f1.w);
    uint4 ph;
    ph.x = *(uint32_t*)&h0; ph.y = *(uint32_t*)&h1;
    ph.z = *(uint32_t*)&h2; ph.w = *(uint32_t*)&h3;
    *(uint4*)(dst + i) = ph;
}

__global__ void pack_bias(const float* __restrict__ a, const float* __restrict__ b,
                          const float* __restrict__ c, float* __restrict__ out) {
    int i = blockIdx.x * 256 + threadIdx.x;
    float v = (i < 1024) ? a[i] : (i < 2048) ? b[i - 1024] : c[i - 2048];
    out[i] = v;
}

// ---------------- PTX helpers ----------------
#define CP16(sa, ga) asm volatile("cp.async.cg.shared.global [%0], [%1], 16;\n" :: "r"(sa), "l"(ga))
#define COMMIT() asm volatile("cp.async.commit_group;\n" ::)
#define LDMX4(r0,r1,r2,r3,addr) asm volatile( \
    "ldmatrix.sync.aligned.m8n8.x4.shared.b16 {%0,%1,%2,%3}, [%4];" \
    : "=r"(r0), "=r"(r1), "=r"(r2), "=r"(r3) : "r"(addr))
#define LDMX4T(r0,r1,r2,r3,addr) asm volatile( \
    "ldmatrix.sync.aligned.m8n8.x4.trans.shared.b16 {%0,%1,%2,%3}, [%4];" \
    : "=r"(r0), "=r"(r1), "=r"(r2), "=r"(r3) : "r"(addr))
#define MMA16816(d, a0,a1,a2,a3, b0,b1) asm volatile( \
    "mma.sync.aligned.m16n8k16.row.col.f32.f16.f16.f32 " \
    "{%0,%1,%2,%3}, {%4,%5,%6,%7}, {%8,%9}, {%0,%1,%2,%3};" \
    : "+f"(d[0]), "+f"(d[1]), "+f"(d[2]), "+f"(d[3]) \
    : "r"(a0), "r"(a1), "r"(a2), "r"(a3), "r"(b0), "r"(b1))

// ---------------- single-term fp16 GEMM ----------------
// BK=64, warp tile 64x64 (4 warps), XOR-swizzled smem (16KB/tile), 3-stage pipeline.
// Swizzle: byte offset within tile = (r*128 + cb) ^ ((r&7)<<4); rows are 128B.
#define TILE_B  16384
#define STAGE_B 32768
#define NSTAGE  3
#define GSMEM_BYTES (NSTAGE * STAGE_B)   // 98304 -> 2 CTAs/SM

__device__ __forceinline__ void g_load_stage(uint32_t smBase, int stg,
                                             const __half* gA, const __half* gB,
                                             int K, int k0, int tid) {
    const uint32_t sb = smBase + (uint32_t)(stg * STAGE_B);
    #pragma unroll
    for (int i = 0; i < 8; i++) {
        const int idx = tid + i * 128;          // [0,1024)
        const int r  = idx >> 3;
        const int cb = (idx & 7) * 16;          // byte column
        const uint32_t sw = (uint32_t)((r * 128 + cb) ^ ((r & 7) << 4));
        const size_t go = (size_t)r * K + k0 + (cb >> 1);
        CP16(sb + sw,          gA + go);
        CP16(sb + TILE_B + sw, gB + go);
    }
    COMMIT();
}

// epi: 2 = bias+residual -> float C ; 3 = bias -> half Ch ; 4 = bias+GELU -> half Ch
__global__ __launch_bounds__(128, 2) void hgemm1t(const __half* __restrict__ A,
                                                  const __half* __restrict__ B,
                                                  const float* __restrict__ bias,
                                                  const float* __restrict__ R,
                                                  float* __restrict__ C,
                                                  __half* __restrict__ Ch,
                                                  int M, int N, int K, int epi) {
    extern __shared__ __half sm16[];

    const int tid  = threadIdx.x;
    const int wid  = tid >> 5;
    const int lane = tid & 31;
    const int bm   = blockIdx.y * 128;
    const int bn   = blockIdx.x * 128;
    const int wm0  = (wid >> 1) * 64;   // 2x2 warp grid, 64x64 each
    const int wn0  = (wid & 1) * 64;

    float acc[4][8][4];
    #pragma unroll
    for (int i = 0; i < 4; i++)
        #pragma unroll
        for (int j = 0; j < 8; j++)
            #pragma unroll
            for (int t = 0; t < 4; t++) acc[i][j][t] = 0.f;

    const int nk = K >> 6;
    const uint32_t smBase = (uint32_t)__cvta_generic_to_shared(sm16);

    const __half* gA = A + (size_t)bm * K;
    const __half* gB = B + (size_t)bn * K;

    g_load_stage(smBase, 0, gA, gB, K, 0, tid);
    g_load_stage(smBase, 1, gA, gB, K, 64, tid);

    const int aRow   = (lane & 15);
    const int fByte0 = ((lane >> 4) << 4);   // 0 or 16 bytes

    int buf = 0, bufw = 2;
    for (int kt = 0; kt < nk; kt++) {
        if (kt + 1 < nk) {
            asm volatile("cp.async.wait_group 1;\n" ::);
        } else {
            asm volatile("cp.async.wait_group 0;\n" ::);
        }
        __syncthreads();
        if (kt + 2 < nk)
            g_load_stage(smBase, bufw, gA, gB, K, (kt + 2) << 6, tid);

        const uint32_t stA = smBase + (uint32_t)(buf * STAGE_B);
        const uint32_t stB = stA + TILE_B;

        #pragma unroll
        for (int ks = 0; ks < 4; ks++) {
            const int cb = ks * 32 + fByte0;   // byte column of fragment
            uint32_t bh[4][4];
            #pragma unroll
            for (int nt2 = 0; nt2 < 4; nt2++) {
                const int rowB = wn0 + nt2 * 16 + aRow;
                const uint32_t sw = (uint32_t)((rowB * 128 + cb) ^ ((rowB & 7) << 4));
                LDMX4(bh[nt2][0], bh[nt2][1], bh[nt2][2], bh[nt2][3], stB + sw);
            }
            #pragma unroll
            for (int mt = 0; mt < 4; mt++) {
                const int rowA = wm0 + mt * 16 + aRow;
                const uint32_t sw = (uint32_t)((rowA * 128 + cb) ^ ((rowA & 7) << 4));
                uint32_t a0, a1, a2, a3;
                LDMX4(a0, a1, a2, a3, stA + sw);
                #pragma unroll
                for (int nt = 0; nt < 8; nt++)
                    MMA16816(acc[mt][nt], a0, a1, a2, a3,
                             bh[nt >> 1][nt & 1], bh[nt >> 1][(nt & 1) + 2]);
            }
        }
        buf  = (buf  == NSTAGE - 1) ? 0 : buf + 1;
        bufw = (bufw == NSTAGE - 1) ? 0 : bufw + 1;
    }

    // ---- epilogue ----
    const int g  = lane >> 2;
    const int tg = lane & 3;
    #pragma unroll
    for (int mt = 0; mt < 4; mt++) {
        #pragma unroll
        for (int nt = 0; nt < 8; nt++) {
            const int col = bn + wn0 + nt * 8 + tg * 2;
            const float bx = bias[col], by = bias[col + 1];
            #pragma unroll
            for (int hh = 0; hh < 2; hh++) {
                const int row = bm + wm0 + mt * 16 + g + hh * 8;
                float v0 = acc[mt][nt][hh * 2 + 0] + bx;
                float v1 = acc[mt][nt][hh * 2 + 1] + by;
                if (epi == 4) {
                    v0 = 0.5f * v0 * (1.0f + erff(v0 * 0.7071067811865475f));
                    v1 = 0.5f * v1 * (1.0f + erff(v1 * 0.7071067811865475f));
                }
                if (epi == 2) {
                    const float2 rv = *(const float2*)&R[(size_t)row * N + col];
                    v0 += rv.x; v1 += rv.y;
                    float2 o; o.x = v0; o.y = v1;
                    *(float2*)&C[(size_t)row * N + col] = o;
                } else {
                    *(__half2*)&Ch[(size_t)row * N + col] = __floats2half2_rn(v0, v1);
                }
            }
        }
    }
}

// ---------------- tensor-core causal flash attention (round-10 version) ----------------
// q-tile 128 (8 warps), key chunk 128, double-buffered K/V.
#define QS 72
#define ATTN_Q_OFF 0
#define ATTN_K_OFF (128 * QS)
#define ATTN_V_OFF (3 * 128 * QS)
#define ATTN_SMEM_BYTES (5 * 128 * QS * 2)   // 92160

__global__ __launch_bounds__(256) void attn_tc(const __half* __restrict__ QKVh,
                                               __half* __restrict__ Oh) {
    extern __shared__ __half asm16[];

    const int bh = blockIdx.y;
    const int b  = bh >> 4;
    const int h  = bh & 15;
    const int q0 = blockIdx.x * 128;
    const int tid  = threadIdx.x;
    const int wq   = tid >> 5;
    const int lane = tid & 31;
    const int g  = lane >> 2;
    const int tg = lane & 3;

    const __half* Qg = QKVh + ((size_t)b * SEQ + q0) * QKVW + h * HDIM;
    const __half* Kg = QKVh + (size_t)b * SEQ * QKVW + DMODEL + h * HDIM;
    const __half* Vg = Kg + DMODEL;

    const uint32_t qB = (uint32_t)__cvta_generic_to_shared(asm16) + ATTN_Q_OFF * 2;
    const uint32_t kB = (uint32_t)__cvta_generic_to_shared(asm16) + ATTN_K_OFF * 2;
    const uint32_t vB = (uint32_t)__cvta_generic_to_shared(asm16) + ATTN_V_OFF * 2;
    const uint32_t bufStride = 128 * QS * 2;

    #pragma unroll
    for (int i = 0; i < 4; i++) {
        int idx = tid + i * 256;
        int r = idx >> 3, sg = (idx & 7) * 8;
        CP16(qB + (r * QS + sg) * 2, Qg + (size_t)r * QKVW + sg);
        CP16(kB + (r * QS + sg) * 2, Kg + (size_t)r * QKVW + sg);
        CP16(vB + (r * QS + sg) * 2, Vg + (size_t)r * QKVW + sg);
    }
    COMMIT();

    uint32_t Qa[4][4];
    float    o[8][4];
    #pragma unroll
    for (int i = 0; i < 8; i++)
        #pragma unroll
        for (int j = 0; j < 4; j++) o[i][j] = 0.f;
    float m0 = -1e30f, m1 = -1e30f, l0 = 0.f, l1 = 0.f;

    const int nchunks = (q0 >> 7) + 1;
    for (int it = 0; it < nchunks; it++) {
        const int buf = it & 1;
        if (it + 1 < nchunks) {
            const int c1 = (it + 1) << 7;
            #pragma unroll
            for (int i = 0; i < 4; i++) {
                int idx = tid + i * 256;
                int r = idx >> 3, sg = (idx & 7) * 8;
                CP16(kB + (buf ^ 1) * bufStride + (r * QS + sg) * 2, Kg + (size_t)(c1 + r) * QKVW + sg);
                CP16(vB + (buf ^ 1) * bufStride + (r * QS + sg) * 2, Vg + (size_t)(c1 + r) * QKVW + sg);
            }
            COMMIT();
            asm volatile("cp.async.wait_group 1;\n" ::);
        } else {
            asm volatile("cp.async.wait_group 0;\n" ::);
        }
        __syncthreads();

        if (it == 0) {
            #pragma unroll
            for (int kk = 0; kk < 4; kk++) {
                uint32_t addr = qB + ((wq * 16 + (lane & 15)) * QS + kk * 16 + ((lane >> 4) << 3)) * 2;
                LDMX4(Qa[kk][0], Qa[kk][1], Qa[kk][2], Qa[kk][3], addr);
            }
        }

        float s[16][4];
        #pragma unroll
        for (int i = 0; i < 16; i++)
            #pragma unroll
            for (int j = 0; j < 4; j++) s[i][j] = 0.f;

        #pragma unroll
        for (int kk = 0; kk < 4; kk++) {
            #pragma unroll
            for (int nt2 = 0; nt2 < 8; nt2++) {
                uint32_t r0, r1, r2, r3;
                uint32_t addr = kB + buf * bufStride +
                    ((nt2 * 16 + (lane & 15)) * QS + kk * 16 + ((lane >> 4) << 3)) * 2;
                LDMX4(r0, r1, r2, r3, addr);
                MMA16816(s[nt2 * 2],     Qa[kk][0], Qa[kk][1], Qa[kk][2], Qa[kk][3], r0, r2);
                MMA16816(s[nt2 * 2 + 1], Qa[kk][0], Qa[kk][1], Qa[kk][2], Qa[kk][3], r1, r3);
            }
        }

        #pragma unroll
        for (int nt = 0; nt < 16; nt++)
            #pragma unroll
            for (int j = 0; j < 4; j++) s[nt][j] *= 0.125f;

        if (it == nchunks - 1) {
            const int row0a = wq * 16 + g;
            const int row1a = row0a + 8;
            #pragma unroll
            for (int nt = 0; nt < 16; nt++) {
                const int key = nt * 8 + 2 * tg;
                if (key     > row0a) s[nt][0] = -1e30f;
                if (key + 1 > row0a) s[nt][1] = -1e30f;
                if (key     > row1a) s[nt][2] = -1e30f;
                if (key + 1 > row1a) s[nt][3] = -1e30f;
            }
        }

        float mx0 = -1e30f, mx1 = -1e30f;
        #pragma unroll
        for (int nt = 0; nt < 16; nt++) {
            mx0 = fmaxf(mx0, fmaxf(s[nt][0], s[nt][1]));
            mx1 = fmaxf(mx1, fmaxf(s[nt][2], s[nt][3]));
        }
        mx0 = fmaxf(mx0, __shfl_xor_sync(0xffffffffu, mx0, 1));
        mx0 = fmaxf(mx0, __shfl_xor_sync(0xffffffffu, mx0, 2));
        mx1 = fmaxf(mx1, __shfl_xor_sync(0xffffffffu, mx1, 1));
        mx1 = fmaxf(mx1, __shfl_xor_sync(0xffffffffu, mx1, 2));
        const float mn0 = fmaxf(m0, mx0), mn1 = fmaxf(m1, mx1);
        const float cr0 = __expf(m0 - mn0), cr1 = __expf(m1 - mn1);
        float ps0 = 0.f, ps1 = 0.f;
        #pragma unroll
        for (int nt = 0; nt < 16; nt++) {
            s[nt][0] = __expf(s[nt][0] - mn0);
            s[nt][1] = __expf(s[nt][1] - mn0);
            s[nt][2] = __expf(s[nt][2] - mn1);
            s[nt][3] = __expf(s[nt][3] - mn1);
            ps0 += s[nt][0] + s[nt][1];
            ps1 += s[nt][2] + s[nt][3];
        }
        ps0 += __shfl_xor_sync(0xffffffffu, ps0, 1);
        ps0 += __shfl_xor_sync(0xffffffffu, ps0, 2);
        ps1 += __shfl_xor_sync(0xffffffffu, ps1, 1);
        ps1 += __shfl_xor_sync(0xffffffffu, ps1, 2);
        l0 = l0 * cr0 + ps0;
        l1 = l1 * cr1 + ps1;
        m0 = mn0; m1 = mn1;
        #pragma unroll
        for (int nd = 0; nd < 8; nd++) {
            o[nd][0] *= cr0; o[nd][1] *= cr0;
            o[nd][2] *= cr1; o[nd][3] *= cr1;
        }

        #pragma unroll
        for (int kk = 0; kk < 8; kk++) {
            __half2 t0 = __floats2half2_rn(s[2*kk][0],   s[2*kk][1]);
            __half2 t1 = __floats2half2_rn(s[2*kk][2],   s[2*kk][3]);
            __half2 t2 = __floats2half2_rn(s[2*kk+1][0], s[2*kk+1][1]);
            __half2 t3 = __floats2half2_rn(s[2*kk+1][2], s[2*kk+1][3]);
            uint32_t pa0 = *(uint32_t*)&t0, pa1 = *(uint32_t*)&t1;
            uint32_t pa2 = *(uint32_t*)&t2, pa3 = *(uint32_t*)&t3;
            #pragma unroll
            for (int nd2 = 0; nd2 < 4; nd2++) {
                uint32_t r0, r1, r2, r3;
                uint32_t addr = vB + buf * bufStride +
                    ((kk * 16 + (lane & 15)) * QS + nd2 * 16 + ((lane >> 4) << 3)) * 2;
                LDMX4T(r0, r1, r2, r3, addr);
                MMA16816(o[nd2 * 2],     pa0, pa1, pa2, pa3, r0, r1);
                MMA16816(o[nd2 * 2 + 1], pa0, pa1, pa2, pa3, r2, r3);
            }
        }
        __syncthreads();
    }

    const float inv0 = 1.f / l0, inv1 = 1.f / l1;
    const int row0 = q0 + wq * 16 + g;
    const size_t ob0 = ((size_t)b * SEQ + row0) * DMODEL + h * HDIM;
    const size_t ob1 = ob0 + 8 * DMODEL;
    #pragma unroll
    for (int nd = 0; nd < 8; nd++) {
        const int d = nd * 8 + 2 * tg;
        *(__half2*)&Oh[ob0 + d] = __floats2half2_rn(o[nd][0] * inv0, o[nd][1] * inv0);
        *(__half2*)&Oh[ob1 + d] = __floats2half2_rn(o[nd][2] * inv1, o[nd][3] * inv1);
    }
}

// ---------------- launcher ----------------
extern "C" void kernel_launch(void* const* d_in, const int* in_sizes, int n_in,
                              void* d_out, int out_size) {
    const float* x     = (const float*)d_in[0];
    const float* Wq    = (const float*)d_in[2];
    const float* bq    = (const float*)d_in[3];
    const float* Wk    = (const float*)d_in[4];
    const float* bk    = (const float*)d_in[5];
    const float* Wv    = (const float*)d_in[6];
    const float* bv    = (const float*)d_in[7];
    const float* Wo    = (const float*)d_in[8];
    const float* bo    = (const float*)d_in[9];
    const float* W1    = (const float*)d_in[10];
    const float* b1    = (const float*)d_in[11];
    const float* W2    = (const float*)d_in[12];
    const float* b2    = (const float*)d_in[13];
    const float* g1    = (const float*)d_in[14];
    const float* beta1 = (const float*)d_in[15];
    const float* g2    = (const float*)d_in[16];
    const float* beta2 = (const float*)d_in[17];
    float* out = (float*)d_out;

    float *x2, *bqkv;
    __half *qkvh, *ah, *hh, *wh;
    cudaGetSymbolAddress((void**)&x2,   g_x2);
    cudaGetSymbolAddress((void**)&bqkv, g_bqkv);
    cudaGetSymbolAddress((void**)&qkvh, g_qkvh);
    cudaGetSymbolAddress((void**)&ah,   g_ah);
    cudaGetSymbolAddress((void**)&hh,   g_hh);
    cudaGetSymbolAddress((void**)&wh,   g_wh);

    static cudaStream_t s2 = nullptr;
    static cudaEvent_t eF, e1, e2, e3, e4;
    static bool init_done = false;
    if (!init_done) {
        cudaFuncSetAttribute(hgemm1t, cudaFuncAttributeMaxDynamicSharedMemorySize, GSMEM_BYTES);
        cudaFuncSetAttribute(attn_tc, cudaFuncAttributeMaxDynamicSharedMemorySize, ATTN_SMEM_BYTES);
        cudaStreamCreateWithFlags(&s2, cudaStreamNonBlocking);
        cudaEventCreateWithFlags(&eF, cudaEventDisableTiming);
        cudaEventCreateWithFlags(&e1, cudaEventDisableTiming);
        cudaEventCreateWithFlags(&e2, cudaEventDisableTiming);
        cudaEventCreateWithFlags(&e3, cudaEventDisableTiming);
        cudaEventCreateWithFlags(&e4, cudaEventDisableTiming);
        init_done = true;
    }

    const int M = MROWS, D = DMODEL, F = FFDIM;
    const size_t DD = (size_t)D * D;
    __half* wqkv = wh;
    __half* wo16 = wh + 3 * DD;
    __half* w116 = wh + 4 * DD;
    __half* w216 = wh + 8 * DD;

    // ---- fork side stream for weight conversions ----
    cudaEventRecord(eF, 0);
    cudaStreamWaitEvent(s2, eF, 0);
    cvt16<<<(int)(DD / 8) / 256, 256, 0, s2>>>(Wq, wqkv);
    cvt16<<<(int)(DD / 8) / 256, 256, 0, s2>>>(Wk, wqkv + DD);
    cvt16<<<(int)(DD / 8) / 256, 256, 0, s2>>>(Wv, wqkv + 2 * DD);
    pack_bias<<<QKVW / 256, 256, 0, s2>>>(bq, bk, bv, bqkv);
    cudaEventRecord(e1, s2);
    cvt16<<<(int)(DD / 8) / 256, 256, 0, s2>>>(Wo, wo16);
    cudaEventRecord(e2, s2);
    cvt16<<<(int)((size_t)F * D / 8) / 256, 256, 0, s2>>>(W1, w116);
    cudaEventRecord(e3, s2);
    cvt16<<<(int)((size_t)D * F / 8) / 256, 256, 0, s2>>>(W2, w216);
    cudaEventRecord(e4, s2);

    // ---- main stream ----
    ln_h16<<<M, 256>>>(x, g1, beta1, ah);

    cudaStreamWaitEvent(0, e1, 0);
    dim3 gQKV(QKVW / 128, M / 128);
    hgemm1t<<<gQKV, 128, GSMEM_BYTES>>>(ah, wqkv, bqkv, nullptr,
                                        nullptr, qkvh, M, QKVW, D, 3);

    dim3 gA(SEQ / 128, BSZ * NHEADS);
    attn_tc<<<gA, 256, ATTN_SMEM_BYTES>>>(qkvh, ah);

    cudaStreamWaitEvent(0, e2, 0);
    dim3 gD(D / 128, M / 128);
    hgemm1t<<<gD, 128, GSMEM_BYTES>>>(ah, wo16, bo, x,
                                      x2, nullptr, M, D, D, 2);

    ln_h16<<<M, 256>>>(x2, g2, beta2, ah);

    cudaStreamWaitEvent(0, e3, 0);
    dim3 gF1(F / 128, M / 128);
    hgemm1t<<<gF1, 128, GSMEM_BYTES>>>(ah, w116, b1, nullptr,
                                       nullptr, hh, M, F, D, 4);

    cudaStreamWaitEvent(0, e4, 0);
    hgemm1t<<<gD, 128, GSMEM_BYTES>>>(hh, w216, b2, x2,
                                      out, nullptr, M, D, F, 2);
}

// round 14
// speedup vs baseline: 1.1750x; 1.0038x over previous
#include <cuda_runtime.h>
#include <cuda_fp16.h>
#include <math.h>
#include <stdint.h>

// ---------------- problem constants ----------------
#define BSZ    2
#define SEQ    2048
#define DMODEL 1024
#define NHEADS 16
#define HDIM   64
#define FFDIM  4096
#define MROWS (BSZ*SEQ)          // 4096
#define QKVW  (3*DMODEL)         // 3072
#define LN_EPS 1e-5f
#define QSCALE 0.18033688011112042f   // 0.125 * log2(e)

// ---------------- scratch (device globals; no allocs) ----------------
__device__ float  g_x2  [MROWS*DMODEL];
__device__ float  g_bqkv[QKVW];
__device__ __half g_qkvh[(size_t)MROWS*QKVW];
__device__ __half g_ah[(size_t)MROWS*DMODEL];        // activations (fp16)
__device__ __half g_hh[(size_t)MROWS*FFDIM];         // FFN hidden (fp16)
__device__ __half g_wh[(size_t)12*1024*1024];        // all weights fp16 (24MB)

// ---------------- LayerNorm -> fp16 directly ----------------
__global__ __launch_bounds__(256) void ln_h16(const float* __restrict__ x,
                                              const float* __restrict__ g,
                                              const float* __restrict__ b,
                                              __half* __restrict__ ah) {
    int row = blockIdx.x;
    int t   = threadIdx.x;
    const float4 v = ((const float4*)(x + (size_t)row * DMODEL))[t];
    float s  = v.x + v.y + v.z + v.w;
    float ss = v.x*v.x + v.y*v.y + v.z*v.z + v.w*v.w;
    #pragma unroll
    for (int o = 16; o; o >>= 1) {
        s  += __shfl_xor_sync(0xffffffffu, s,  o);
        ss += __shfl_xor_sync(0xffffffffu, ss, o);
    }
    __shared__ float rs[8], rss[8];
    if ((t & 31) == 0) { rs[t >> 5] = s; rss[t >> 5] = ss; }
    __syncthreads();
    float S = 0.f, SS = 0.f;
    #pragma unroll
    for (int i = 0; i < 8; i++) { S += rs[i]; SS += rss[i]; }
    float mean = S * (1.f / DMODEL);
    float var  = SS * (1.f / DMODEL) - mean * mean;
    float rstd = rsqrtf(var + LN_EPS);
    const float4 gv = ((const float4*)g)[t];
    const float4 bv = ((const float4*)b)[t];
    float o0 = (v.x - mean) * rstd * gv.x + bv.x;
    float o1 = (v.y - mean) * rstd * gv.y + bv.y;
    float o2 = (v.z - mean) * rstd * gv.z + bv.z;
    float o3 = (v.w - mean) * rstd * gv.w + bv.w;
    __half2* ph = (__half2*)(ah + (size_t)row * DMODEL);
    ph[t*2]   = __floats2half2_rn(o0, o1);
    ph[t*2+1] = __floats2half2_rn(o2, o3);
}

// ---------------- fp32 -> fp16 convert (weights), 8 elems/thread ----------------
__global__ __launch_bounds__(256) void cvt16(const float* __restrict__ src,
                                             __half* __restrict__ dst) {
    size_t i = ((size_t)blockIdx.x * 256 + threadIdx.x) * 8;
    const float4 f0 = *(const float4*)(src + i);
    const float4 f1 = *(const float4*)(src + i + 4);
    __half2 h0 = __floats2half2_rn(f0.x, f0.y);
    __half2 h1 = __floats2half2_rn(f0.z, f0.w);
    __half2 h2 = __floats2half2_rn(f1.x, f1.y);
    __half2 h3 = __floats2half2_rn(f1.z, f1.w);
    uint4 ph;
    ph.x = *(uint32_t*)&h0; ph.y = *(uint32_t*)&h1;
    ph.z = *(uint32_t*)&h2; ph.w = *(uint32_t*)&h3;
    *(uint4*)(dst + i) = ph;
}

__global__ void pack_bias(const float* __restrict__ a, const float* __restrict__ b,
                          const float* __restrict__ c, float* __restrict__ out) {
    int i = blockIdx.x * 256 + threadIdx.x;
    float v = (i < 1024) ? a[i] : (i < 2048) ? b[i - 1024] : c[i - 2048];
    out[i] = v;
}

// ---------------- PTX helpers ----------------
#define CP16(sa, ga) asm volatile("cp.async.cg.shared.global [%0], [%1], 16;\n" :: "r"(sa), "l"(ga))
#define COMMIT() asm volatile("cp.async.commit_group;\n" ::)
#define LDMX4(r0,r1,r2,r3,addr) asm volatile( \
    "ldmatrix.sync.aligned.m8n8.x4.shared.b16 {%0,%1,%2,%3}, [%4];" \
    : "=r"(r0), "=r"(r1), "=r"(r2), "=r"(r3) : "r"(addr))
#define LDMX4T(r0,r1,r2,r3,addr) asm volatile( \
    "ldmatrix.sync.aligned.m8n8.x4.trans.shared.b16 {%0,%1,%2,%3}, [%4];" \
    : "=r"(r0), "=r"(r1), "=r"(r2), "=r"(r3) : "r"(addr))
#define MMA16816(d, a0,a1,a2,a3, b0,b1) asm volatile( \
    "mma.sync.aligned.m16n8k16.row.col.f32.f16.f16.f32 " \
    "{%0,%1,%2,%3}, {%4,%5,%6,%7}, {%8,%9}, {%0,%1,%2,%3};" \
    : "+f"(d[0]), "+f"(d[1]), "+f"(d[2]), "+f"(d[3]) \
    : "r"(a0), "r"(a1), "r"(a2), "r"(a3), "r"(b0), "r"(b1))

__device__ __forceinline__ float ex2f(float x) {
    float y;
    asm("ex2.approx.f32 %0, %1;" : "=f"(y) : "f"(x));
    return y;
}

// ---------------- single-term fp16 GEMM ----------------
// BK=64, warp tile 64x64 (4 warps), XOR-swizzled smem (16KB/tile), 3-stage pipeline.
#define TILE_B  16384
#define STAGE_B 32768
#define NSTAGE  3
#define GSMEM_BYTES (NSTAGE * STAGE_B)   // 98304 -> 2 CTAs/SM

__device__ __forceinline__ void g_load_stage(uint32_t smBase, int stg,
                                             const __half* gA, const __half* gB,
                                             int K, int k0, int tid) {
    const uint32_t sb = smBase + (uint32_t)(stg * STAGE_B);
    #pragma unroll
    for (int i = 0; i < 8; i++) {
        const int idx = tid + i * 128;          // [0,1024)
        const int r  = idx >> 3;
        const int cb = (idx & 7) * 16;          // byte column
        const uint32_t sw = (uint32_t)((r * 128 + cb) ^ ((r & 7) << 4));
        const size_t go = (size_t)r * K + k0 + (cb >> 1);
        CP16(sb + sw,          gA + go);
        CP16(sb + TILE_B + sw, gB + go);
    }
    COMMIT();
}

// epi: 2 = bias+residual -> float C ; 3 = bias (+Q-scale for col<1024) -> half Ch ;
//      4 = bias+GELU -> half Ch
__global__ __launch_bounds__(128, 2) void hgemm1t(const __half* __restrict__ A,
                                                  const __half* __restrict__ B,
                                                  const float* __restrict__ bias,
                                                  const float* __restrict__ R,
                                                  float* __restrict__ C,
                                                  __half* __restrict__ Ch,
                                                  int M, int N, int K, int epi) {
    extern __shared__ __half sm16[];

    const int tid  = threadIdx.x;
    const int wid  = tid >> 5;
    const int lane = tid & 31;
    const int bm   = blockIdx.y * 128;
    const int bn   = blockIdx.x * 128;
    const int wm0  = (wid >> 1) * 64;
    const int wn0  = (wid & 1) * 64;

    float acc[4][8][4];
    #pragma unroll
    for (int i = 0; i < 4; i++)
        #pragma unroll
        for (int j = 0; j < 8; j++)
            #pragma unroll
            for (int t = 0; t < 4; t++) acc[i][j][t] = 0.f;

    const int nk = K >> 6;
    const uint32_t smBase = (uint32_t)__cvta_generic_to_shared(sm16);

    const __half* gA = A + (size_t)bm * K;
    const __half* gB = B + (size_t)bn * K;

    g_load_stage(smBase, 0, gA, gB, K, 0, tid);
    g_load_stage(smBase, 1, gA, gB, K, 64, tid);

    const int aRow   = (lane & 15);
    const int fByte0 = ((lane >> 4) << 4);

    int buf = 0, bufw = 2;
    for (int kt = 0; kt < nk; kt++) {
        if (kt + 1 < nk) {
            asm volatile("cp.async.wait_group 1;\n" ::);
        } else {
            asm volatile("cp.async.wait_group 0;\n" ::);
        }
        __syncthreads();
        if (kt + 2 < nk)
            g_load_stage(smBase, bufw, gA, gB, K, (kt + 2) << 6, tid);

        const uint32_t stA = smBase + (uint32_t)(buf * STAGE_B);
        const uint32_t stB = stA + TILE_B;

        #pragma unroll
        for (int ks = 0; ks < 4; ks++) {
            const int cb = ks * 32 + fByte0;
            uint32_t bh[4][4];
            #pragma unroll
            for (int nt2 = 0; nt2 < 4; nt2++) {
                const int rowB = wn0 + nt2 * 16 + aRow;
                const uint32_t sw = (uint32_t)((rowB * 128 + cb) ^ ((rowB & 7) << 4));
                LDMX4(bh[nt2][0], bh[nt2][1], bh[nt2][2], bh[nt2][3], stB + sw);
            }
            #pragma unroll
            for (int mt = 0; mt < 4; mt++) {
                const int rowA = wm0 + mt * 16 + aRow;
                const uint32_t sw = (uint32_t)((rowA * 128 + cb) ^ ((rowA & 7) << 4));
                uint32_t a0, a1, a2, a3;
                LDMX4(a0, a1, a2, a3, stA + sw);
                #pragma unroll
                for (int nt = 0; nt < 8; nt++)
                    MMA16816(acc[mt][nt], a0, a1, a2, a3,
                             bh[nt >> 1][nt & 1], bh[nt >> 1][(nt & 1) + 2]);
            }
        }
        buf  = (buf  == NSTAGE - 1) ? 0 : buf + 1;
        bufw = (bufw == NSTAGE - 1) ? 0 : bufw + 1;
    }

    // ---- epilogue ----
    const int g  = lane >> 2;
    const int tg = lane & 3;
    #pragma unroll
    for (int mt = 0; mt < 4; mt++) {
        #pragma unroll
        for (int nt = 0; nt < 8; nt++) {
            const int col = bn + wn0 + nt * 8 + tg * 2;
            const float bx = bias[col], by = bias[col + 1];
            #pragma unroll
            for (int hh = 0; hh < 2; hh++) {
                const int row = bm + wm0 + mt * 16 + g + hh * 8;
                float v0 = acc[mt][nt][hh * 2 + 0] + bx;
                float v1 = acc[mt][nt][hh * 2 + 1] + by;
                if (epi == 4) {
                    v0 = 0.5f * v0 * (1.0f + erff(v0 * 0.7071067811865475f));
                    v1 = 0.5f * v1 * (1.0f + erff(v1 * 0.7071067811865475f));
                }
                if (epi == 2) {
                    const float2 rv = *(const float2*)&R[(size_t)row * N + col];
                    v0 += rv.x; v1 += rv.y;
                    float2 o; o.x = v0; o.y = v1;
                    *(float2*)&C[(size_t)row * N + col] = o;
                } else {
                    if (epi == 3 && col < DMODEL) {   // pre-scale Q for base-2 softmax
                        v0 *= QSCALE; v1 *= QSCALE;
                    }
                    *(__half2*)&Ch[(size_t)row * N + col] = __floats2half2_rn(v0, v1);
                }
            }
        }
    }
}

// ---------------- tensor-core causal flash attention ----------------
// q-tile 128 (8 warps), key chunk 128, double-buffered K/V.
// Q pre-scaled by 0.125*log2(e); base-2 softmax (ex2.approx).
// Diagonal chunk PEELED out of the hot loop: masking & triangular skip only there.
#define QS 72
#define ATTN_Q_OFF 0
#define ATTN_K_OFF (128 * QS)
#define ATTN_V_OFF (3 * 128 * QS)
#define ATTN_SMEM_BYTES (5 * 128 * QS * 2)   // 92160

__global__ __launch_bounds__(256) void attn_tc(const __half* __restrict__ QKVh,
                                               __half* __restrict__ Oh) {
    extern __shared__ __half asm16[];

    const int bh = blockIdx.y;
    const int b  = bh >> 4;
    const int h  = bh & 15;
    const int q0 = blockIdx.x * 128;
    const int tid  = threadIdx.x;
    const int wq   = tid >> 5;
    const int lane = tid & 31;
    const int g  = lane >> 2;
    const int tg = lane & 3;

    const __half* Qg = QKVh + ((size_t)b * SEQ + q0) * QKVW + h * HDIM;
    const __half* Kg = QKVh + (size_t)b * SEQ * QKVW + DMODEL + h * HDIM;
    const __half* Vg = Kg + DMODEL;

    const uint32_t qB = (uint32_t)__cvta_generic_to_shared(asm16) + ATTN_Q_OFF * 2;
    const uint32_t kB = (uint32_t)__cvta_generic_to_shared(asm16) + ATTN_K_OFF * 2;
    const uint32_t vB = (uint32_t)__cvta_generic_to_shared(asm16) + ATTN_V_OFF * 2;
    const uint32_t bufStride = 128 * QS * 2;

    #pragma unroll
    for (int i = 0; i < 4; i++) {
        int idx = tid + i * 256;
        int r = idx >> 3, sg = (idx & 7) * 8;
        CP16(qB + (r * QS + sg) * 2, Qg + (size_t)r * QKVW + sg);
        CP16(kB + (r * QS + sg) * 2, Kg + (size_t)r * QKVW + sg);
        CP16(vB + (r * QS + sg) * 2, Vg + (size_t)r * QKVW + sg);
    }
    COMMIT();

    uint32_t Qa[4][4];
    float    o[8][4];
    #pragma unroll
    for (int i = 0; i < 8; i++)
        #pragma unroll
        for (int j = 0; j < 4; j++) o[i][j] = 0.f;
    float m0 = -1e30f, m1 = -1e30f, l0 = 0.f, l1 = 0.f;

    const int nchunks = (q0 >> 7) + 1;

    // ---- main loop: chunks [0, nchunks-1), no masking ----
    for (int it = 0; it < nchunks - 1; it++) {
        const int buf = it & 1;
        {
            const int c1 = (it + 1) << 7;
            #pragma unroll
            for (int i = 0; i < 4; i++) {
                int idx = tid + i * 256;
                int r = idx >> 3, sg = (idx & 7) * 8;
                CP16(kB + (buf ^ 1) * bufStride + (r * QS + sg) * 2, Kg + (size_t)(c1 + r) * QKVW + sg);
                CP16(vB + (buf ^ 1) * bufStride + (r * QS + sg) * 2, Vg + (size_t)(c1 + r) * QKVW + sg);
            }
            COMMIT();
            asm volatile("cp.async.wait_group 1;\n" ::);
        }
        __syncthreads();

        if (it == 0) {
            #pragma unroll
            for (int kk = 0; kk < 4; kk++) {
                uint32_t addr = qB + ((wq * 16 + (lane & 15)) * QS + kk * 16 + ((lane >> 4) << 3)) * 2;
                LDMX4(Qa[kk][0], Qa[kk][1], Qa[kk][2], Qa[kk][3], addr);
            }
        }

        float s[16][4];
        #pragma unroll
        for (int i = 0; i < 16; i++)
            #pragma unroll
            for (int j = 0; j < 4; j++) s[i][j] = 0.f;

        #pragma unroll
        for (int kk = 0; kk < 4; kk++) {
            #pragma unroll
            for (int nt2 = 0; nt2 < 8; nt2++) {
                uint32_t r0, r1, r2, r3;
                uint32_t addr = kB + buf * bufStride +
                    ((nt2 * 16 + (lane & 15)) * QS + kk * 16 + ((lane >> 4) << 3)) * 2;
                LDMX4(r0, r1, r2, r3, addr);
                MMA16816(s[nt2 * 2],     Qa[kk][0], Qa[kk][1], Qa[kk][2], Qa[kk][3], r0, r2);
                MMA16816(s[nt2 * 2 + 1], Qa[kk][0], Qa[kk][1], Qa[kk][2], Qa[kk][3], r1, r3);
            }
        }

        float mx0 = -1e30f, mx1 = -1e30f;
        #pragma unroll
        for (int nt = 0; nt < 16; nt++) {
            mx0 = fmaxf(mx0, fmaxf(s[nt][0], s[nt][1]));
            mx1 = fmaxf(mx1, fmaxf(s[nt][2], s[nt][3]));
        }
        mx0 = fmaxf(mx0, __shfl_xor_sync(0xffffffffu, mx0, 1));
        mx0 = fmaxf(mx0, __shfl_xor_sync(0xffffffffu, mx0, 2));
        mx1 = fmaxf(mx1, __shfl_xor_sync(0xffffffffu, mx1, 1));
        mx1 = fmaxf(mx1, __shfl_xor_sync(0xffffffffu, mx1, 2));
        const float mn0 = fmaxf(m0, mx0), mn1 = fmaxf(m1, mx1);
        const float cr0 = ex2f(m0 - mn0), cr1 = ex2f(m1 - mn1);
        float ps0 = 0.f, ps1 = 0.f;
        #pragma unroll
        for (int nt = 0; nt < 16; nt++) {
            s[nt][0] = ex2f(s[nt][0] - mn0);
            s[nt][1] = ex2f(s[nt][1] - mn0);
            s[nt][2] = ex2f(s[nt][2] - mn1);
            s[nt][3] = ex2f(s[nt][3] - mn1);
            ps0 += s[nt][0] + s[nt][1];
            ps1 += s[nt][2] + s[nt][3];
        }
        ps0 += __shfl_xor_sync(0xffffffffu, ps0, 1);
        ps0 += __shfl_xor_sync(0xffffffffu, ps0, 2);
        ps1 += __shfl_xor_sync(0xffffffffu, ps1, 1);
        ps1 += __shfl_xor_sync(0xffffffffu, ps1, 2);
        l0 = l0 * cr0 + ps0;
        l1 = l1 * cr1 + ps1;
        m0 = mn0; m1 = mn1;
        #pragma unroll
        for (int nd = 0; nd < 8; nd++) {
            o[nd][0] *= cr0; o[nd][1] *= cr0;
            o[nd][2] *= cr1; o[nd][3] *= cr1;
        }

        #pragma unroll
        for (int kk = 0; kk < 8; kk++) {
            __half2 t0 = __floats2half2_rn(s[2*kk][0],   s[2*kk][1]);
            __half2 t1 = __floats2half2_rn(s[2*kk][2],   s[2*kk][3]);
            __half2 t2 = __floats2half2_rn(s[2*kk+1][0], s[2*kk+1][1]);
            __half2 t3 = __floats2half2_rn(s[2*kk+1][2], s[2*kk+1][3]);
            uint32_t pa0 = *(uint32_t*)&t0, pa1 = *(uint32_t*)&t1;
            uint32_t pa2 = *(uint32_t*)&t2, pa3 = *(uint32_t*)&t3;
            #pragma unroll
            for (int nd2 = 0; nd2 < 4; nd2++) {
                uint32_t r0, r1, r2, r3;
                uint32_t addr = vB + buf * bufStride +
                    ((kk * 16 + (lane & 15)) * QS + nd2 * 16 + ((lane >> 4) << 3)) * 2;
                LDMX4T(r0, r1, r2, r3, addr);
                MMA16816(o[nd2 * 2],     pa0, pa1, pa2, pa3, r0, r1);
                MMA16816(o[nd2 * 2 + 1], pa0, pa1, pa2, pa3, r2, r3);
            }
        }
        __syncthreads();
    }

    // ---- peeled diagonal chunk (it = nchunks-1) ----
    {
        const int buf = (nchunks - 1) & 1;
        asm volatile("cp.async.wait_group 0;\n" ::);
        __syncthreads();

        if (nchunks == 1) {
            #pragma unroll
            for (int kk = 0; kk < 4; kk++) {
                uint32_t addr = qB + ((wq * 16 + (lane & 15)) * QS + kk * 16 + ((lane >> 4) << 3)) * 2;
                LDMX4(Qa[kk][0], Qa[kk][1], Qa[kk][2], Qa[kk][3], addr);
            }
        }

        float s[16][4];
        #pragma unroll
        for (int i = 0; i < 16; i++)
            #pragma unroll
            for (int j = 0; j < 4; j++) s[i][j] = 0.f;

        // only key blocks nt2 <= wq can be unmasked
        #pragma unroll
        for (int kk = 0; kk < 4; kk++) {
            #pragma unroll
            for (int nt2 = 0; nt2 < 8; nt2++) {
                if (nt2 > wq) continue;
                uint32_t r0, r1, r2, r3;
                uint32_t addr = kB + buf * bufStride +
                    ((nt2 * 16 + (lane & 15)) * QS + kk * 16 + ((lane >> 4) << 3)) * 2;
                LDMX4(r0, r1, r2, r3, addr);
                MMA16816(s[nt2 * 2],     Qa[kk][0], Qa[kk][1], Qa[kk][2], Qa[kk][3], r0, r2);
                MMA16816(s[nt2 * 2 + 1], Qa[kk][0], Qa[kk][1], Qa[kk][2], Qa[kk][3], r1, r3);
            }
        }

        // causal mask (also forces skipped blocks to -inf)
        {
            const int row0a = wq * 16 + g;
            const int row1a = row0a + 8;
            #pragma unroll
            for (int nt = 0; nt < 16; nt++) {
                const int key = nt * 8 + 2 * tg;
                if (key     > row0a) s[nt][0] = -1e30f;
                if (key + 1 > row0a) s[nt][1] = -1e30f;
                if (key     > row1a) s[nt][2] = -1e30f;
                if (key + 1 > row1a) s[nt][3] = -1e30f;
            }
        }

        float mx0 = -1e30f, mx1 = -1e30f;
        #pragma unroll
        for (int nt = 0; nt < 16; nt++) {
            mx0 = fmaxf(mx0, fmaxf(s[nt][0], s[nt][1]));
            mx1 = fmaxf(mx1, fmaxf(s[nt][2], s[nt][3]));
        }
        mx0 = fmaxf(mx0, __shfl_xor_sync(0xffffffffu, mx0, 1));
        mx0 = fmaxf(mx0, __shfl_xor_sync(0xffffffffu, mx0, 2));
        mx1 = fmaxf(mx1, __shfl_xor_sync(0xffffffffu, mx1, 1));
        mx1 = fmaxf(mx1, __shfl_xor_sync(0xffffffffu, mx1, 2));
        const float mn0 = fmaxf(m0, mx0), mn1 = fmaxf(m1, mx1);
        const float cr0 = ex2f(m0 - mn0), cr1 = ex2f(m1 - mn1);
        float ps0 = 0.f, ps1 = 0.f;
        #pragma unroll
        for (int nt = 0; nt < 16; nt++) {
            s[nt][0] = ex2f(s[nt][0] - mn0);
            s[nt][1] = ex2f(s[nt][1] - mn0);
            s[nt][2] = ex2f(s[nt][2] - mn1);
            s[nt][3] = ex2f(s[nt][3] - mn1);
            ps0 += s[nt][0] + s[nt][1];
            ps1 += s[nt][2] + s[nt][3];
        }
        ps0 += __shfl_xor_sync(0xffffffffu, ps0, 1);
        ps0 += __shfl_xor_sync(0xffffffffu, ps0, 2);
        ps1 += __shfl_xor_sync(0xffffffffu, ps1, 1);
        ps1 += __shfl_xor_sync(0xffffffffu, ps1, 2);
        l0 = l0 * cr0 + ps0;
        l1 = l1 * cr1 + ps1;
        #pragma unroll
        for (int nd = 0; nd < 8; nd++) {
            o[nd][0] *= cr0; o[nd][1] *= cr0;
            o[nd][2] *= cr1; o[nd][3] *= cr1;
        }

        // PV: only kk <= wq contributes (P exactly 0 above diagonal)
        #pragma unroll
        for (int kk = 0; kk < 8; kk++) {
            if (kk > wq) continue;
            __half2 t0 = __floats2half2_rn(s[2*kk][0],   s[2*kk][1]);
            __half2 t1 = __floats2half2_rn(s[2*kk][2],   s[2*kk][3]);
            __half2 t2 = __floats2half2_rn(s[2*kk+1][0], s[2*kk+1][1]);
            __half2 t3 = __floats2half2_rn(s[2*kk+1][2], s[2*kk+1][3]);
            uint32_t pa0 = *(uint32_t*)&t0, pa1 = *(uint32_t*)&t1;
            uint32_t pa2 = *(uint32_t*)&t2, pa3 = *(uint32_t*)&t3;
            #pragma unroll
            for (int nd2 = 0; nd2 < 4; nd2++) {
                uint32_t r0, r1, r2, r3;
                uint32_t addr = vB + buf * bufStride +
                    ((kk * 16 + (lane & 15)) * QS + nd2 * 16 + ((lane >> 4) << 3)) * 2;
                LDMX4T(r0, r1, r2, r3, addr);
                MMA16816(o[nd2 * 2],     pa0, pa1, pa2, pa3, r0, r1);
                MMA16816(o[nd2 * 2 + 1], pa0, pa1, pa2, pa3, r2, r3);
            }
        }
    }

    const float inv0 = 1.f / l0, inv1 = 1.f / l1;
    const int row0 = q0 + wq * 16 + g;
    const size_t ob0 = ((size_t)b * SEQ + row0) * DMODEL + h * HDIM;
    const size_t ob1 = ob0 + 8 * DMODEL;
    #pragma unroll
    for (int nd = 0; nd < 8; nd++) {
        const int d = nd * 8 + 2 * tg;
        *(__half2*)&Oh[ob0 + d] = __floats2half2_rn(o[nd][0] * inv0, o[nd][1] * inv0);
        *(__half2*)&Oh[ob1 + d] = __floats2half2_rn(o[nd][2] * inv1, o[nd][3] * inv1);
    }
}

// ---------------- launcher ----------------
extern "C" void kernel_launch(void* const* d_in, const int* in_sizes, int n_in,
                              void* d_out, int out_size) {
    const float* x     = (const float*)d_in[0];
    const float* Wq    = (const float*)d_in[2];
    const float* bq    = (const float*)d_in[3];
    const float* Wk    = (const float*)d_in[4];
    const float* bk    = (const float*)d_in[5];
    const float* Wv    = (const float*)d_in[6];
    const float* bv    = (const float*)d_in[7];
    const float* Wo    = (const float*)d_in[8];
    const float* bo    = (const float*)d_in[9];
    const float* W1    = (const float*)d_in[10];
    const float* b1    = (const float*)d_in[11];
    const float* W2    = (const float*)d_in[12];
    const float* b2    = (const float*)d_in[13];
    const float* g1    = (const float*)d_in[14];
    const float* beta1 = (const float*)d_in[15];
    const float* g2    = (const float*)d_in[16];
    const float* beta2 = (const float*)d_in[17];
    float* out = (float*)d_out;

    float *x2, *bqkv;
    __half *qkvh, *ah, *hh, *wh;
    cudaGetSymbolAddress((void**)&x2,   g_x2);
    cudaGetSymbolAddress((void**)&bqkv, g_bqkv);
    cudaGetSymbolAddress((void**)&qkvh, g_qkvh);
    cudaGetSymbolAddress((void**)&ah,   g_ah);
    cudaGetSymbolAddress((void**)&hh,   g_hh);
    cudaGetSymbolAddress((void**)&wh,   g_wh);

    static cudaStream_t s2 = nullptr;
    static cudaEvent_t eF, e1, e2, e3, e4;
    static bool init_done = false;
    if (!init_done) {
        cudaFuncSetAttribute(hgemm1t, cudaFuncAttributeMaxDynamicSharedMemorySize, GSMEM_BYTES);
        cudaFuncSetAttribute(attn_tc, cudaFuncAttributeMaxDynamicSharedMemorySize, ATTN_SMEM_BYTES);
        cudaStreamCreateWithFlags(&s2, cudaStreamNonBlocking);
        cudaEventCreateWithFlags(&eF, cudaEventDisableTiming);
        cudaEventCreateWithFlags(&e1, cudaEventDisableTiming);
        cudaEventCreateWithFlags(&e2, cudaEventDisableTiming);
        cudaEventCreateWithFlags(&e3, cudaEventDisableTiming);
        cudaEventCreateWithFlags(&e4, cudaEventDisableTiming);
        init_done = true;
    }

    const int M = MROWS, D = DMODEL, F = FFDIM;
    const size_t DD = (size_t)D * D;
    __half* wqkv = wh;
    __half* wo16 = wh + 3 * DD;
    __half* w116 = wh + 4 * DD;
    __half* w216 = wh + 8 * DD;

    // ---- fork side stream for weight conversions ----
    cudaEventRecord(eF, 0);
    cudaStreamWaitEvent(s2, eF, 0);
    cvt16<<<(int)(DD / 8) / 256, 256, 0, s2>>>(Wq, wqkv);
    cvt16<<<(int)(DD / 8) / 256, 256, 0, s2>>>(Wk, wqkv + DD);
    cvt16<<<(int)(DD / 8) / 256, 256, 0, s2>>>(Wv, wqkv + 2 * DD);
    pack_bias<<<QKVW / 256, 256, 0, s2>>>(bq, bk, bv, bqkv);
    cudaEventRecord(e1, s2);
    cvt16<<<(int)(DD / 8) / 256, 256, 0, s2>>>(Wo, wo16);
    cudaEventRecord(e2, s2);
    cvt16<<<(int)((size_t)F * D / 8) / 256, 256, 0, s2>>>(W1, w116);
    cudaEventRecord(e3, s2);
    cvt16<<<(int)((size_t)D * F / 8) / 256, 256, 0, s2>>>(W2, w216);
    cudaEventRecord(e4, s2);

    // ---- main stream ----
    ln_h16<<<M, 256>>>(x, g1, beta1, ah);

    cudaStreamWaitEvent(0, e1, 0);
    dim3 gQKV(QKVW / 128, M / 128);
    hgemm1t<<<gQKV, 128, GSMEM_BYTES>>>(ah, wqkv, bqkv, nullptr,
                                        nullptr, qkvh, M, QKVW, D, 3);

    dim3 gA(SEQ / 128, BSZ * NHEADS);
    attn_tc<<<gA, 256, ATTN_SMEM_BYTES>>>(qkvh, ah);

    cudaStreamWaitEvent(0, e2, 0);
    dim3 gD(D / 128, M / 128);
    hgemm1t<<<gD, 128, GSMEM_BYTES>>>(ah, wo16, bo, x,
                                      x2, nullptr, M, D, D, 2);

    ln_h16<<<M, 256>>>(x2, g2, beta2, ah);

    cudaStreamWaitEvent(0, e3, 0);
    dim3 gF1(F / 128, M / 128);
    hgemm1t<<<gF1, 128, GSMEM_BYTES>>>(ah, w116, b1, nullptr,
                                       nullptr, hh, M, F, D, 4);

    cudaStreamWaitEvent(0, e4, 0);
    hgemm1t<<<gD, 128, GSMEM_BYTES>>>(hh, w216, b2, x2,
                                      out, nullptr, M, D, F, 2);
}

// round 15
// speedup vs baseline: 1.2082x; 1.0283x over previous
#include <cuda_runtime.h>
#include <cuda_fp16.h>
#include <math.h>
#include <stdint.h>

// ---------------- problem constants ----------------
#define BSZ    2
#define SEQ    2048
#define DMODEL 1024
#define NHEADS 16
#define HDIM   64
#define FFDIM  4096
#define MROWS (BSZ*SEQ)          // 4096
#define QKVW  (3*DMODEL)         // 3072
#define LN_EPS 1e-5f
#define QSCALE 0.18033688011112042f   // 0.125 * log2(e)

// ---------------- scratch (device globals; no allocs) ----------------
__device__ float  g_x2  [MROWS*DMODEL];
__device__ float  g_bqkv[QKVW];
__device__ __half g_qkvh[(size_t)MROWS*QKVW];
__device__ __half g_ah[(size_t)MROWS*DMODEL];        // activations (fp16)
__device__ __half g_hh[(size_t)MROWS*FFDIM];         // FFN hidden (fp16)
__device__ __half g_wh[(size_t)12*1024*1024];        // all weights fp16 (24MB)

// ---------------- LayerNorm -> fp16 directly ----------------
__global__ __launch_bounds__(256) void ln_h16(const float* __restrict__ x,
                                              const float* __restrict__ g,
                                              const float* __restrict__ b,
                                              __half* __restrict__ ah) {
    int row = blockIdx.x;
    int t   = threadIdx.x;
    const float4 v = ((const float4*)(x + (size_t)row * DMODEL))[t];
    float s  = v.x + v.y + v.z + v.w;
    float ss = v.x*v.x + v.y*v.y + v.z*v.z + v.w*v.w;
    #pragma unroll
    for (int o = 16; o; o >>= 1) {
        s  += __shfl_xor_sync(0xffffffffu, s,  o);
        ss += __shfl_xor_sync(0xffffffffu, ss, o);
    }
    __shared__ float rs[8], rss[8];
    if ((t & 31) == 0) { rs[t >> 5] = s; rss[t >> 5] = ss; }
    __syncthreads();
    float S = 0.f, SS = 0.f;
    #pragma unroll
    for (int i = 0; i < 8; i++) { S += rs[i]; SS += rss[i]; }
    float mean = S * (1.f / DMODEL);
    float var  = SS * (1.f / DMODEL) - mean * mean;
    float rstd = rsqrtf(var + LN_EPS);
    const float4 gv = ((const float4*)g)[t];
    const float4 bv = ((const float4*)b)[t];
    float o0 = (v.x - mean) * rstd * gv.x + bv.x;
    float o1 = (v.y - mean) * rstd * gv.y + bv.y;
    float o2 = (v.z - mean) * rstd * gv.z + bv.z;
    float o3 = (v.w - mean) * rstd * gv.w + bv.w;
    __half2* ph = (__half2*)(ah + (size_t)row * DMODEL);
    ph[t*2]   = __floats2half2_rn(o0, o1);
    ph[t*2+1] = __floats2half2_rn(o2, o3);
}

// ---------------- fp32 -> fp16 convert (weights), 8 elems/thread ----------------
__global__ __launch_bounds__(256) void cvt16(const float* __restrict__ src,
                                             __half* __restrict__ dst) {
    size_t i = ((size_t)blockIdx.x * 256 + threadIdx.x) * 8;
    const float4 f0 = *(const float4*)(src + i);
    const float4 f1 = *(const float4*)(src + i + 4);
    __half2 h0 = __floats2half2_rn(f0.x, f0.y);
    __half2 h1 = __floats2half2_rn(f0.z, f0.w);
    __half2 h2 = __floats2half2_rn(f1.x, f1.y);
    __half2 h3 = __floats2half2_rn(f1.z, f1.w);
    uint4 ph;
    ph.x = *(uint32_t*)&h0; ph.y = *(uint32_t*)&h1;
    ph.z = *(uint32_t*)&h2; ph.w = *(uint32_t*)&h3;
    *(uint4*)(dst + i) = ph;
}

__global__ void pack_bias(const float* __restrict__ a, const float* __restrict__ b,
                          const float* __restrict__ c, float* __restrict__ out) {
    int i = blockIdx.x * 256 + threadIdx.x;
    float v = (i < 1024) ? a[i] : (i < 2048) ? b[i - 1024] : c[i - 2048];
    out[i] = v;
}

// ---------------- PTX helpers ----------------
#define CP16(sa, ga) asm volatile("cp.async.cg.shared.global [%0], [%1], 16;\n" :: "r"(sa), "l"(ga))
#define COMMIT() asm volatile("cp.async.commit_group;\n" ::)
#define LDMX4(r0,r1,r2,r3,addr) asm volatile( \
    "ldmatrix.sync.aligned.m8n8.x4.shared.b16 {%0,%1,%2,%3}, [%4];" \
    : "=r"(r0), "=r"(r1), "=r"(r2), "=r"(r3) : "r"(addr))
#define LDMX4T(r0,r1,r2,r3,addr) asm volatile( \
    "ldmatrix.sync.aligned.m8n8.x4.trans.shared.b16 {%0,%1,%2,%3}, [%4];" \
    : "=r"(r0), "=r"(r1), "=r"(r2), "=r"(r3) : "r"(addr))
#define MMA16816(d, a0,a1,a2,a3, b0,b1) asm volatile( \
    "mma.sync.aligned.m16n8k16.row.col.f32.f16.f16.f32 " \
    "{%0,%1,%2,%3}, {%4,%5,%6,%7}, {%8,%9}, {%0,%1,%2,%3};" \
    : "+f"(d[0]), "+f"(d[1]), "+f"(d[2]), "+f"(d[3]) \
    : "r"(a0), "r"(a1), "r"(a2), "r"(a3), "r"(b0), "r"(b1))

__device__ __forceinline__ float ex2f(float x) {
    float y;
    asm("ex2.approx.f32 %0, %1;" : "=f"(y) : "f"(x));
    return y;
}

// ---------------- single-term fp16 GEMM ----------------
// BK=64, warp tile 64x64 (4 warps), XOR-swizzled smem (16KB/tile), 3-stage pipeline.
#define TILE_B  16384
#define STAGE_B 32768
#define NSTAGE  3
#define GSMEM_BYTES (NSTAGE * STAGE_B)   // 98304 -> 2 CTAs/SM

__device__ __forceinline__ void g_load_stage(uint32_t smBase, int stg,
                                             const __half* gA, const __half* gB,
                                             int K, int k0, int tid) {
    const uint32_t sb = smBase + (uint32_t)(stg * STAGE_B);
    #pragma unroll
    for (int i = 0; i < 8; i++) {
        const int idx = tid + i * 128;          // [0,1024)
        const int r  = idx >> 3;
        const int cb = (idx & 7) * 16;          // byte column
        const uint32_t sw = (uint32_t)((r * 128 + cb) ^ ((r & 7) << 4));
        const size_t go = (size_t)r * K + k0 + (cb >> 1);
        CP16(sb + sw,          gA + go);
        CP16(sb + TILE_B + sw, gB + go);
    }
    COMMIT();
}

// epi: 2 = bias+residual -> float C ; 3 = bias (+Q-scale for col<1024) -> half Ch ;
//      4 = bias+GELU -> half Ch
__global__ __launch_bounds__(128, 2) void hgemm1t(const __half* __restrict__ A,
                                                  const __half* __restrict__ B,
                                                  const float* __restrict__ bias,
                                                  const float* __restrict__ R,
                                                  float* __restrict__ C,
                                                  __half* __restrict__ Ch,
                                                  int M, int N, int K, int epi) {
    extern __shared__ __half sm16[];

    const int tid  = threadIdx.x;
    const int wid  = tid >> 5;
    const int lane = tid & 31;
    const int bm   = blockIdx.y * 128;
    const int bn   = blockIdx.x * 128;
    const int wm0  = (wid >> 1) * 64;
    const int wn0  = (wid & 1) * 64;

    float acc[4][8][4];
    #pragma unroll
    for (int i = 0; i < 4; i++)
        #pragma unroll
        for (int j = 0; j < 8; j++)
            #pragma unroll
            for (int t = 0; t < 4; t++) acc[i][j][t] = 0.f;

    const int nk = K >> 6;
    const uint32_t smBase = (uint32_t)__cvta_generic_to_shared(sm16);

    const __half* gA = A + (size_t)bm * K;
    const __half* gB = B + (size_t)bn * K;

    g_load_stage(smBase, 0, gA, gB, K, 0, tid);
    g_load_stage(smBase, 1, gA, gB, K, 64, tid);

    const int aRow   = (lane & 15);
    const int fByte0 = ((lane >> 4) << 4);

    int buf = 0, bufw = 2;
    for (int kt = 0; kt < nk; kt++) {
        if (kt + 1 < nk) {
            asm volatile("cp.async.wait_group 1;\n" ::);
        } else {
            asm volatile("cp.async.wait_group 0;\n" ::);
        }
        __syncthreads();
        if (kt + 2 < nk)
            g_load_stage(smBase, bufw, gA, gB, K, (kt + 2) << 6, tid);

        const uint32_t stA = smBase + (uint32_t)(buf * STAGE_B);
        const uint32_t stB = stA + TILE_B;

        #pragma unroll
        for (int ks = 0; ks < 4; ks++) {
            const int cb = ks * 32 + fByte0;
            uint32_t bh[4][4];
            #pragma unroll
            for (int nt2 = 0; nt2 < 4; nt2++) {
                const int rowB = wn0 + nt2 * 16 + aRow;
                const uint32_t sw = (uint32_t)((rowB * 128 + cb) ^ ((rowB & 7) << 4));
                LDMX4(bh[nt2][0], bh[nt2][1], bh[nt2][2], bh[nt2][3], stB + sw);
            }
            #pragma unroll
            for (int mt = 0; mt < 4; mt++) {
                const int rowA = wm0 + mt * 16 + aRow;
                const uint32_t sw = (uint32_t)((rowA * 128 + cb) ^ ((rowA & 7) << 4));
                uint32_t a0, a1, a2, a3;
                LDMX4(a0, a1, a2, a3, stA + sw);
                #pragma unroll
                for (int nt = 0; nt < 8; nt++)
                    MMA16816(acc[mt][nt], a0, a1, a2, a3,
                             bh[nt >> 1][nt & 1], bh[nt >> 1][(nt & 1) + 2]);
            }
        }
        buf  = (buf  == NSTAGE - 1) ? 0 : buf + 1;
        bufw = (bufw == NSTAGE - 1) ? 0 : bufw + 1;
    }

    // ---- epilogue ----
    const int g  = lane >> 2;
    const int tg = lane & 3;
    #pragma unroll
    for (int mt = 0; mt < 4; mt++) {
        #pragma unroll
        for (int nt = 0; nt < 8; nt++) {
            const int col = bn + wn0 + nt * 8 + tg * 2;
            const float bx = bias[col], by = bias[col + 1];
            #pragma unroll
            for (int hh = 0; hh < 2; hh++) {
                const int row = bm + wm0 + mt * 16 + g + hh * 8;
                float v0 = acc[mt][nt][hh * 2 + 0] + bx;
                float v1 = acc[mt][nt][hh * 2 + 1] + by;
                if (epi == 4) {
                    v0 = 0.5f * v0 * (1.0f + erff(v0 * 0.7071067811865475f));
                    v1 = 0.5f * v1 * (1.0f + erff(v1 * 0.7071067811865475f));
                }
                if (epi == 2) {
                    const float2 rv = *(const float2*)&R[(size_t)row * N + col];
                    v0 += rv.x; v1 += rv.y;
                    float2 o; o.x = v0; o.y = v1;
                    *(float2*)&C[(size_t)row * N + col] = o;
                } else {
                    if (epi == 3 && col < DMODEL) {
                        v0 *= QSCALE; v1 *= QSCALE;
                    }
                    *(__half2*)&Ch[(size_t)row * N + col] = __floats2half2_rn(v0, v1);
                }
            }
        }
    }
}

// ---------------- tensor-core causal flash attention ----------------
// Balanced pairing: each CTA handles q-tile blockIdx.x AND q-tile (NT-1-blockIdx.x)
// sequentially -> uniform 17-chunk workload, 256 CTAs = one balanced wave.
// q-tile 128 (8 warps), key chunk 128, double-buffered K/V, base-2 softmax,
// diagonal chunk peeled (triangular block skip).
#define QS 72
#define ATTN_Q_OFF 0
#define ATTN_K_OFF (128 * QS)
#define ATTN_V_OFF (3 * 128 * QS)
#define ATTN_SMEM_BYTES (5 * 128 * QS * 2)   // 92160
#define NQT (SEQ / 128)                      // 16

__global__ __launch_bounds__(256) void attn_tc(const __half* __restrict__ QKVh,
                                               __half* __restrict__ Oh) {
    extern __shared__ __half asm16[];

    const int bh = blockIdx.y;
    const int b  = bh >> 4;
    const int h  = bh & 15;
    const int tid  = threadIdx.x;
    const int wq   = tid >> 5;
    const int lane = tid & 31;
    const int g  = lane >> 2;
    const int tg = lane & 3;

    const __half* Kg = QKVh + (size_t)b * SEQ * QKVW + DMODEL + h * HDIM;
    const __half* Vg = Kg + DMODEL;

    const uint32_t qB = (uint32_t)__cvta_generic_to_shared(asm16) + ATTN_Q_OFF * 2;
    const uint32_t kB = (uint32_t)__cvta_generic_to_shared(asm16) + ATTN_K_OFF * 2;
    const uint32_t vB = (uint32_t)__cvta_generic_to_shared(asm16) + ATTN_V_OFF * 2;
    const uint32_t bufStride = 128 * QS * 2;

    for (int pass = 0; pass < 2; pass++) {
        const int qi = pass == 0 ? blockIdx.x : (NQT - 1 - blockIdx.x);
        const int q0 = qi * 128;
        const int nchunks = qi + 1;

        const __half* Qg = QKVh + ((size_t)b * SEQ + q0) * QKVW + h * HDIM;

        // load Q tile + chunk0 K/V
        #pragma unroll
        for (int i = 0; i < 4; i++) {
            int idx = tid + i * 256;
            int r = idx >> 3, sg = (idx & 7) * 8;
            CP16(qB + (r * QS + sg) * 2, Qg + (size_t)r * QKVW + sg);
            CP16(kB + (r * QS + sg) * 2, Kg + (size_t)r * QKVW + sg);
            CP16(vB + (r * QS + sg) * 2, Vg + (size_t)r * QKVW + sg);
        }
        COMMIT();

        uint32_t Qa[4][4];
        float    o[8][4];
        #pragma unroll
        for (int i = 0; i < 8; i++)
            #pragma unroll
            for (int j = 0; j < 4; j++) o[i][j] = 0.f;
        float m0 = -1e30f, m1 = -1e30f, l0 = 0.f, l1 = 0.f;

        // ---- main loop: chunks [0, nchunks-1), no masking ----
        for (int it = 0; it < nchunks - 1; it++) {
            const int buf = it & 1;
            {
                const int c1 = (it + 1) << 7;
                #pragma unroll
                for (int i = 0; i < 4; i++) {
                    int idx = tid + i * 256;
                    int r = idx >> 3, sg = (idx & 7) * 8;
                    CP16(kB + (buf ^ 1) * bufStride + (r * QS + sg) * 2, Kg + (size_t)(c1 + r) * QKVW + sg);
                    CP16(vB + (buf ^ 1) * bufStride + (r * QS + sg) * 2, Vg + (size_t)(c1 + r) * QKVW + sg);
                }
                COMMIT();
                asm volatile("cp.async.wait_group 1;\n" ::);
            }
            __syncthreads();

            if (it == 0) {
                #pragma unroll
                for (int kk = 0; kk < 4; kk++) {
                    uint32_t addr = qB + ((wq * 16 + (lane & 15)) * QS + kk * 16 + ((lane >> 4) << 3)) * 2;
                    LDMX4(Qa[kk][0], Qa[kk][1], Qa[kk][2], Qa[kk][3], addr);
                }
            }

            float s[16][4];
            #pragma unroll
            for (int i = 0; i < 16; i++)
                #pragma unroll
                for (int j = 0; j < 4; j++) s[i][j] = 0.f;

            #pragma unroll
            for (int kk = 0; kk < 4; kk++) {
                #pragma unroll
                for (int nt2 = 0; nt2 < 8; nt2++) {
                    uint32_t r0, r1, r2, r3;
                    uint32_t addr = kB + buf * bufStride +
                        ((nt2 * 16 + (lane & 15)) * QS + kk * 16 + ((lane >> 4) << 3)) * 2;
                    LDMX4(r0, r1, r2, r3, addr);
                    MMA16816(s[nt2 * 2],     Qa[kk][0], Qa[kk][1], Qa[kk][2], Qa[kk][3], r0, r2);
                    MMA16816(s[nt2 * 2 + 1], Qa[kk][0], Qa[kk][1], Qa[kk][2], Qa[kk][3], r1, r3);
                }
            }

            float mx0 = -1e30f, mx1 = -1e30f;
            #pragma unroll
            for (int nt = 0; nt < 16; nt++) {
                mx0 = fmaxf(mx0, fmaxf(s[nt][0], s[nt][1]));
                mx1 = fmaxf(mx1, fmaxf(s[nt][2], s[nt][3]));
            }
            mx0 = fmaxf(mx0, __shfl_xor_sync(0xffffffffu, mx0, 1));
            mx0 = fmaxf(mx0, __shfl_xor_sync(0xffffffffu, mx0, 2));
            mx1 = fmaxf(mx1, __shfl_xor_sync(0xffffffffu, mx1, 1));
            mx1 = fmaxf(mx1, __shfl_xor_sync(0xffffffffu, mx1, 2));
            const float mn0 = fmaxf(m0, mx0), mn1 = fmaxf(m1, mx1);
            const float cr0 = ex2f(m0 - mn0), cr1 = ex2f(m1 - mn1);
            float ps0 = 0.f, ps1 = 0.f;
            #pragma unroll
            for (int nt = 0; nt < 16; nt++) {
                s[nt][0] = ex2f(s[nt][0] - mn0);
                s[nt][1] = ex2f(s[nt][1] - mn0);
                s[nt][2] = ex2f(s[nt][2] - mn1);
                s[nt][3] = ex2f(s[nt][3] - mn1);
                ps0 += s[nt][0] + s[nt][1];
                ps1 += s[nt][2] + s[nt][3];
            }
            ps0 += __shfl_xor_sync(0xffffffffu, ps0, 1);
            ps0 += __shfl_xor_sync(0xffffffffu, ps0, 2);
            ps1 += __shfl_xor_sync(0xffffffffu, ps1, 1);
            ps1 += __shfl_xor_sync(0xffffffffu, ps1, 2);
            l0 = l0 * cr0 + ps0;
            l1 = l1 * cr1 + ps1;
            m0 = mn0; m1 = mn1;
            #pragma unroll
            for (int nd = 0; nd < 8; nd++) {
                o[nd][0] *= cr0; o[nd][1] *= cr0;
                o[nd][2] *= cr1; o[nd][3] *= cr1;
            }

            #pragma unroll
            for (int kk = 0; kk < 8; kk++) {
                __half2 t0 = __floats2half2_rn(s[2*kk][0],   s[2*kk][1]);
                __half2 t1 = __floats2half2_rn(s[2*kk][2],   s[2*kk][3]);
                __half2 t2 = __floats2half2_rn(s[2*kk+1][0], s[2*kk+1][1]);
                __half2 t3 = __floats2half2_rn(s[2*kk+1][2], s[2*kk+1][3]);
                uint32_t pa0 = *(uint32_t*)&t0, pa1 = *(uint32_t*)&t1;
                uint32_t pa2 = *(uint32_t*)&t2, pa3 = *(uint32_t*)&t3;
                #pragma unroll
                for (int nd2 = 0; nd2 < 4; nd2++) {
                    uint32_t r0, r1, r2, r3;
                    uint32_t addr = vB + buf * bufStride +
                        ((kk * 16 + (lane & 15)) * QS + nd2 * 16 + ((lane >> 4) << 3)) * 2;
                    LDMX4T(r0, r1, r2, r3, addr);
                    MMA16816(o[nd2 * 2],     pa0, pa1, pa2, pa3, r0, r1);
                    MMA16816(o[nd2 * 2 + 1], pa0, pa1, pa2, pa3, r2, r3);
                }
            }
            __syncthreads();
        }

        // ---- peeled diagonal chunk ----
        {
            const int buf = (nchunks - 1) & 1;
            asm volatile("cp.async.wait_group 0;\n" ::);
            __syncthreads();

            if (nchunks == 1) {
                #pragma unroll
                for (int kk = 0; kk < 4; kk++) {
                    uint32_t addr = qB + ((wq * 16 + (lane & 15)) * QS + kk * 16 + ((lane >> 4) << 3)) * 2;
                    LDMX4(Qa[kk][0], Qa[kk][1], Qa[kk][2], Qa[kk][3], addr);
                }
            }

            float s[16][4];
            #pragma unroll
            for (int i = 0; i < 16; i++)
                #pragma unroll
                for (int j = 0; j < 4; j++) s[i][j] = 0.f;

            #pragma unroll
            for (int kk = 0; kk < 4; kk++) {
                #pragma unroll
                for (int nt2 = 0; nt2 < 8; nt2++) {
                    if (nt2 > wq) continue;
                    uint32_t r0, r1, r2, r3;
                    uint32_t addr = kB + buf * bufStride +
                        ((nt2 * 16 + (lane & 15)) * QS + kk * 16 + ((lane >> 4) << 3)) * 2;
                    LDMX4(r0, r1, r2, r3, addr);
                    MMA16816(s[nt2 * 2],     Qa[kk][0], Qa[kk][1], Qa[kk][2], Qa[kk][3], r0, r2);
                    MMA16816(s[nt2 * 2 + 1], Qa[kk][0], Qa[kk][1], Qa[kk][2], Qa[kk][3], r1, r3);
                }
            }

            {
                const int row0a = wq * 16 + g;
                const int row1a = row0a + 8;
                #pragma unroll
                for (int nt = 0; nt < 16; nt++) {
                    const int key = nt * 8 + 2 * tg;
                    if (key     > row0a) s[nt][0] = -1e30f;
                    if (key + 1 > row0a) s[nt][1] = -1e30f;
                    if (key     > row1a) s[nt][2] = -1e30f;
                    if (key + 1 > row1a) s[nt][3] = -1e30f;
                }
            }

            float mx0 = -1e30f, mx1 = -1e30f;
            #pragma unroll
            for (int nt = 0; nt < 16; nt++) {
                mx0 = fmaxf(mx0, fmaxf(s[nt][0], s[nt][1]));
                mx1 = fmaxf(mx1, fmaxf(s[nt][2], s[nt][3]));
            }
            mx0 = fmaxf(mx0, __shfl_xor_sync(0xffffffffu, mx0, 1));
            mx0 = fmaxf(mx0, __shfl_xor_sync(0xffffffffu, mx0, 2));
            mx1 = fmaxf(mx1, __shfl_xor_sync(0xffffffffu, mx1, 1));
            mx1 = fmaxf(mx1, __shfl_xor_sync(0xffffffffu, mx1, 2));
            const float mn0 = fmaxf(m0, mx0), mn1 = fmaxf(m1, mx1);
            const float cr0 = ex2f(m0 - mn0), cr1 = ex2f(m1 - mn1);
            float ps0 = 0.f, ps1 = 0.f;
            #pragma unroll
            for (int nt = 0; nt < 16; nt++) {
                s[nt][0] = ex2f(s[nt][0] - mn0);
                s[nt][1] = ex2f(s[nt][1] - mn0);
                s[nt][2] = ex2f(s[nt][2] - mn1);
                s[nt][3] = ex2f(s[nt][3] - mn1);
                ps0 += s[nt][0] + s[nt][1];
                ps1 += s[nt][2] + s[nt][3];
            }
            ps0 += __shfl_xor_sync(0xffffffffu, ps0, 1);
            ps0 += __shfl_xor_sync(0xffffffffu, ps0, 2);
            ps1 += __shfl_xor_sync(0xffffffffu, ps1, 1);
            ps1 += __shfl_xor_sync(0xffffffffu, ps1, 2);
            l0 = l0 * cr0 + ps0;
            l1 = l1 * cr1 + ps1;
            #pragma unroll
            for (int nd = 0; nd < 8; nd++) {
                o[nd][0] *= cr0; o[nd][1] *= cr0;
                o[nd][2] *= cr1; o[nd][3] *= cr1;
            }

            #pragma unroll
            for (int kk = 0; kk < 8; kk++) {
                if (kk > wq) continue;
                __half2 t0 = __floats2half2_rn(s[2*kk][0],   s[2*kk][1]);
                __half2 t1 = __floats2half2_rn(s[2*kk][2],   s[2*kk][3]);
                __half2 t2 = __floats2half2_rn(s[2*kk+1][0], s[2*kk+1][1]);
                __half2 t3 = __floats2half2_rn(s[2*kk+1][2], s[2*kk+1][3]);
                uint32_t pa0 = *(uint32_t*)&t0, pa1 = *(uint32_t*)&t1;
                uint32_t pa2 = *(uint32_t*)&t2, pa3 = *(uint32_t*)&t3;
                #pragma unroll
                for (int nd2 = 0; nd2 < 4; nd2++) {
                    uint32_t r0, r1, r2, r3;
                    uint32_t addr = vB + buf * bufStride +
                        ((kk * 16 + (lane & 15)) * QS + nd2 * 16 + ((lane >> 4) << 3)) * 2;
                    LDMX4T(r0, r1, r2, r3, addr);
                    MMA16816(o[nd2 * 2],     pa0, pa1, pa2, pa3, r0, r1);
                    MMA16816(o[nd2 * 2 + 1], pa0, pa1, pa2, pa3, r2, r3);
                }
            }
        }

        // ---- epilogue for this q-tile ----
        const float inv0 = 1.f / l0, inv1 = 1.f / l1;
        const int row0 = q0 + wq * 16 + g;
        const size_t ob0 = ((size_t)b * SEQ + row0) * DMODEL + h * HDIM;
        const size_t ob1 = ob0 + 8 * DMODEL;
        #pragma unroll
        for (int nd = 0; nd < 8; nd++) {
            const int d = nd * 8 + 2 * tg;
            *(__half2*)&Oh[ob0 + d] = __floats2half2_rn(o[nd][0] * inv0, o[nd][1] * inv0);
            *(__half2*)&Oh[ob1 + d] = __floats2half2_rn(o[nd][2] * inv1, o[nd][3] * inv1);
        }
        __syncthreads();   // smem reuse safety before next pass
    }
}

// ---------------- launcher ----------------
extern "C" void kernel_launch(void* const* d_in, const int* in_sizes, int n_in,
                              void* d_out, int out_size) {
    const float* x     = (const float*)d_in[0];
    const float* Wq    = (const float*)d_in[2];
    const float* bq    = (const float*)d_in[3];
    const float* Wk    = (const float*)d_in[4];
    const float* bk    = (const float*)d_in[5];
    const float* Wv    = (const float*)d_in[6];
    const float* bv    = (const float*)d_in[7];
    const float* Wo    = (const float*)d_in[8];
    const float* bo    = (const float*)d_in[9];
    const float* W1    = (const float*)d_in[10];
    const float* b1    = (const float*)d_in[11];
    const float* W2    = (const float*)d_in[12];
    const float* b2    = (const float*)d_in[13];
    const float* g1    = (const float*)d_in[14];
    const float* beta1 = (const float*)d_in[15];
    const float* g2    = (const float*)d_in[16];
    const float* beta2 = (const float*)d_in[17];
    float* out = (float*)d_out;

    float *x2, *bqkv;
    __half *qkvh, *ah, *hh, *wh;
    cudaGetSymbolAddress((void**)&x2,   g_x2);
    cudaGetSymbolAddress((void**)&bqkv, g_bqkv);
    cudaGetSymbolAddress((void**)&qkvh, g_qkvh);
    cudaGetSymbolAddress((void**)&ah,   g_ah);
    cudaGetSymbolAddress((void**)&hh,   g_hh);
    cudaGetSymbolAddress((void**)&wh,   g_wh);

    static cudaStream_t s2 = nullptr;
    static cudaEvent_t eF, e1, e2, e3, e4;
    static bool init_done = false;
    if (!init_done) {
        cudaFuncSetAttribute(hgemm1t, cudaFuncAttributeMaxDynamicSharedMemorySize, GSMEM_BYTES);
        cudaFuncSetAttribute(attn_tc, cudaFuncAttributeMaxDynamicSharedMemorySize, ATTN_SMEM_BYTES);
        cudaStreamCreateWithFlags(&s2, cudaStreamNonBlocking);
        cudaEventCreateWithFlags(&eF, cudaEventDisableTiming);
        cudaEventCreateWithFlags(&e1, cudaEventDisableTiming);
        cudaEventCreateWithFlags(&e2, cudaEventDisableTiming);
        cudaEventCreateWithFlags(&e3, cudaEventDisableTiming);
        cudaEventCreateWithFlags(&e4, cudaEventDisableTiming);
        init_done = true;
    }

    const int M = MROWS, D = DMODEL, F = FFDIM;
    const size_t DD = (size_t)D * D;
    __half* wqkv = wh;
    __half* wo16 = wh + 3 * DD;
    __half* w116 = wh + 4 * DD;
    __half* w216 = wh + 8 * DD;

    // ---- fork side stream for weight conversions ----
    cudaEventRecord(eF, 0);
    cudaStreamWaitEvent(s2, eF, 0);
    cvt16<<<(int)(DD / 8) / 256, 256, 0, s2>>>(Wq, wqkv);
    cvt16<<<(int)(DD / 8) / 256, 256, 0, s2>>>(Wk, wqkv + DD);
    cvt16<<<(int)(DD / 8) / 256, 256, 0, s2>>>(Wv, wqkv + 2 * DD);
    pack_bias<<<QKVW / 256, 256, 0, s2>>>(bq, bk, bv, bqkv);
    cudaEventRecord(e1, s2);
    cvt16<<<(int)(DD / 8) / 256, 256, 0, s2>>>(Wo, wo16);
    cudaEventRecord(e2, s2);
    cvt16<<<(int)((size_t)F * D / 8) / 256, 256, 0, s2>>>(W1, w116);
    cudaEventRecord(e3, s2);
    cvt16<<<(int)((size_t)D * F / 8) / 256, 256, 0, s2>>>(W2, w216);
    cudaEventRecord(e4, s2);

    // ---- main stream ----
    ln_h16<<<M, 256>>>(x, g1, beta1, ah);

    cudaStreamWaitEvent(0, e1, 0);
    dim3 gQKV(QKVW / 128, M / 128);
    hgemm1t<<<gQKV, 128, GSMEM_BYTES>>>(ah, wqkv, bqkv, nullptr,
                                        nullptr, qkvh, M, QKVW, D, 3);

    dim3 gA(NQT / 2, BSZ * NHEADS);
    attn_tc<<<gA, 256, ATTN_SMEM_BYTES>>>(qkvh, ah);

    cudaStreamWaitEvent(0, e2, 0);
    dim3 gD(D / 128, M / 128);
    hgemm1t<<<gD, 128, GSMEM_BYTES>>>(ah, wo16, bo, x,
                                      x2, nullptr, M, D, D, 2);

    ln_h16<<<M, 256>>>(x2, g2, beta2, ah);

    cudaStreamWaitEvent(0, e3, 0);
    dim3 gF1(F / 128, M / 128);
    hgemm1t<<<gF1, 128, GSMEM_BYTES>>>(ah, w116, b1, nullptr,
                                       nullptr, hh, M, F, D, 4);

    cudaStreamWaitEvent(0, e4, 0);
    hgemm1t<<<gD, 128, GSMEM_BYTES>>>(hh, w216, b2, x2,
                                      out, nullptr, M, D, F, 2);
}

// round 16
// speedup vs baseline: 1.2306x; 1.0185x over previous
#include <cuda_runtime.h>
#include <cuda_fp16.h>
#include <math.h>
#include <stdint.h>

// ---------------- problem constants ----------------
#define BSZ    2
#define SEQ    2048
#define DMODEL 1024
#define NHEADS 16
#define HDIM   64
#define FFDIM  4096
#define MROWS (BSZ*SEQ)          // 4096
#define QKVW  (3*DMODEL)         // 3072
#define LN_EPS 1e-5f
#define QSCALE 0.18033688011112042f   // 0.125 * log2(e)
#define ONES_H2 0x3C003C00u

// ---------------- scratch (device globals; no allocs) ----------------
__device__ float  g_x2  [MROWS*DMODEL];
__device__ float  g_bqkv[QKVW];
__device__ __half g_qkvh[(size_t)MROWS*QKVW];
__device__ __half g_ah[(size_t)MROWS*DMODEL];        // activations (fp16)
__device__ __half g_hh[(size_t)MROWS*FFDIM];         // FFN hidden (fp16)
__device__ __half g_wh[(size_t)12*1024*1024];        // all weights fp16 (24MB)

// ---------------- LayerNorm -> fp16 directly ----------------
__global__ __launch_bounds__(256) void ln_h16(const float* __restrict__ x,
                                              const float* __restrict__ g,
                                              const float* __restrict__ b,
                                              __half* __restrict__ ah) {
    int row = blockIdx.x;
    int t   = threadIdx.x;
    const float4 v = ((const float4*)(x + (size_t)row * DMODEL))[t];
    float s  = v.x + v.y + v.z + v.w;
    float ss = v.x*v.x + v.y*v.y + v.z*v.z + v.w*v.w;
    #pragma unroll
    for (int o = 16; o; o >>= 1) {
        s  += __shfl_xor_sync(0xffffffffu, s,  o);
        ss += __shfl_xor_sync(0xffffffffu, ss, o);
    }
    __shared__ float rs[8], rss[8];
    if ((t & 31) == 0) { rs[t >> 5] = s; rss[t >> 5] = ss; }
    __syncthreads();
    float S = 0.f, SS = 0.f;
    #pragma unroll
    for (int i = 0; i < 8; i++) { S += rs[i]; SS += rss[i]; }
    float mean = S * (1.f / DMODEL);
    float var  = SS * (1.f / DMODEL) - mean * mean;
    float rstd = rsqrtf(var + LN_EPS);
    const float4 gv = ((const float4*)g)[t];
    const float4 bv = ((const float4*)b)[t];
    float o0 = (v.x - mean) * rstd * gv.x + bv.x;
    float o1 = (v.y - mean) * rstd * gv.y + bv.y;
    float o2 = (v.z - mean) * rstd * gv.z + bv.z;
    float o3 = (v.w - mean) * rstd * gv.w + bv.w;
    __half2* ph = (__half2*)(ah + (size_t)row * DMODEL);
    ph[t*2]   = __floats2half2_rn(o0, o1);
    ph[t*2+1] = __floats2half2_rn(o2, o3);
}

// ---------------- fp32 -> fp16 convert (weights), 8 elems/thread ----------------
__global__ __launch_bounds__(256) void cvt16(const float* __restrict__ src,
                                             __half* __restrict__ dst) {
    size_t i = ((size_t)blockIdx.x * 256 + threadIdx.x) * 8;
    const float4 f0 = *(const float4*)(src + i);
    const float4 f1 = *(const float4*)(src + i + 4);
    __half2 h0 = __floats2half2_rn(f0.x, f0.y);
    __half2 h1 = __floats2half2_rn(f0.z, f0.w);
    __half2 h2 = __floats2half2_rn(f1.x, f1.y);
    __half2 h3 = __floats2half2_rn(f1.z, f1.w);
    uint4 ph;
    ph.x = *(uint32_t*)&h0; ph.y = *(uint32_t*)&h1;
    ph.z = *(uint32_t*)&h2; ph.w = *(uint32_t*)&h3;
    *(uint4*)(dst + i) = ph;
}

__global__ void pack_bias(const float* __restrict__ a, const float* __restrict__ b,
                          const float* __restrict__ c, float* __restrict__ out) {
    int i = blockIdx.x * 256 + threadIdx.x;
    float v = (i < 1024) ? a[i] : (i < 2048) ? b[i - 1024] : c[i - 2048];
    out[i] = v;
}

// ---------------- PTX helpers ----------------
#define CP16(sa, ga) asm volatile("cp.async.cg.shared.global [%0], [%1], 16;\n" :: "r"(sa), "l"(ga))
#define COMMIT() asm volatile("cp.async.commit_group;\n" ::)
#define LDMX4(r0,r1,r2,r3,addr) asm volatile( \
    "ldmatrix.sync.aligned.m8n8.x4.shared.b16 {%0,%1,%2,%3}, [%4];" \
    : "=r"(r0), "=r"(r1), "=r"(r2), "=r"(r3) : "r"(addr))
#define LDMX4T(r0,r1,r2,r3,addr) asm volatile( \
    "ldmatrix.sync.aligned.m8n8.x4.trans.shared.b16 {%0,%1,%2,%3}, [%4];" \
    : "=r"(r0), "=r"(r1), "=r"(r2), "=r"(r3) : "r"(addr))
#define MMA16816(d, a0,a1,a2,a3, b0,b1) asm volatile( \
    "mma.sync.aligned.m16n8k16.row.col.f32.f16.f16.f32 " \
    "{%0,%1,%2,%3}, {%4,%5,%6,%7}, {%8,%9}, {%0,%1,%2,%3};" \
    : "+f"(d[0]), "+f"(d[1]), "+f"(d[2]), "+f"(d[3]) \
    : "r"(a0), "r"(a1), "r"(a2), "r"(a3), "r"(b0), "r"(b1))

__device__ __forceinline__ float ex2f(float x) {
    float y;
    asm("ex2.approx.f32 %0, %1;" : "=f"(y) : "f"(x));
    return y;
}
__device__ __forceinline__ uint32_t h2ex2(uint32_t x) {
    uint32_t y;
    asm("ex2.approx.f16x2 %0, %1;" : "=r"(y) : "r"(x));
    return y;
}
__device__ __forceinline__ uint32_t packh2(float a, float b) {
    __half2 t = __floats2half2_rn(a, b);
    return *(uint32_t*)&t;
}

// ---------------- single-term fp16 GEMM ----------------
// BK=64, warp tile 64x64 (4 warps), XOR-swizzled smem (16KB/tile), 3-stage pipeline.
#define TILE_B  16384
#define STAGE_B 32768
#define NSTAGE  3
#define GSMEM_BYTES (NSTAGE * STAGE_B)   // 98304 -> 2 CTAs/SM

__device__ __forceinline__ void g_load_stage(uint32_t smBase, int stg,
                                             const __half* gA, const __half* gB,
                                             int K, int k0, int tid) {
    const uint32_t sb = smBase + (uint32_t)(stg * STAGE_B);
    #pragma unroll
    for (int i = 0; i < 8; i++) {
        const int idx = tid + i * 128;          // [0,1024)
        const int r  = idx >> 3;
        const int cb = (idx & 7) * 16;          // byte column
        const uint32_t sw = (uint32_t)((r * 128 + cb) ^ ((r & 7) << 4));
        const size_t go = (size_t)r * K + k0 + (cb >> 1);
        CP16(sb + sw,          gA + go);
        CP16(sb + TILE_B + sw, gB + go);
    }
    COMMIT();
}

// epi: 2 = bias+residual -> float C ; 3 = bias (+Q-scale for col<1024) -> half Ch ;
//      4 = bias+GELU -> half Ch
__global__ __launch_bounds__(128, 2) void hgemm1t(const __half* __restrict__ A,
                                                  const __half* __restrict__ B,
                                                  const float* __restrict__ bias,
                                                  const float* __restrict__ R,
                                                  float* __restrict__ C,
                                                  __half* __restrict__ Ch,
                                                  int M, int N, int K, int epi) {
    extern __shared__ __half sm16[];

    const int tid  = threadIdx.x;
    const int wid  = tid >> 5;
    const int lane = tid & 31;
    const int bm   = blockIdx.y * 128;
    const int bn   = blockIdx.x * 128;
    const int wm0  = (wid >> 1) * 64;
    const int wn0  = (wid & 1) * 64;

    float acc[4][8][4];
    #pragma unroll
    for (int i = 0; i < 4; i++)
        #pragma unroll
        for (int j = 0; j < 8; j++)
            #pragma unroll
            for (int t = 0; t < 4; t++) acc[i][j][t] = 0.f;

    const int nk = K >> 6;
    const uint32_t smBase = (uint32_t)__cvta_generic_to_shared(sm16);

    const __half* gA = A + (size_t)bm * K;
    const __half* gB = B + (size_t)bn * K;

    g_load_stage(smBase, 0, gA, gB, K, 0, tid);
    g_load_stage(smBase, 1, gA, gB, K, 64, tid);

    const int aRow   = (lane & 15);
    const int fByte0 = ((lane >> 4) << 4);

    int buf = 0, bufw = 2;
    for (int kt = 0; kt < nk; kt++) {
        if (kt + 1 < nk) {
            asm volatile("cp.async.wait_group 1;\n" ::);
        } else {
            asm volatile("cp.async.wait_group 0;\n" ::);
        }
        __syncthreads();
        if (kt + 2 < nk)
            g_load_stage(smBase, bufw, gA, gB, K, (kt + 2) << 6, tid);

        const uint32_t stA = smBase + (uint32_t)(buf * STAGE_B);
        const uint32_t stB = stA + TILE_B;

        #pragma unroll
        for (int ks = 0; ks < 4; ks++) {
            const int cb = ks * 32 + fByte0;
            uint32_t bh[4][4];
            #pragma unroll
            for (int nt2 = 0; nt2 < 4; nt2++) {
                const int rowB = wn0 + nt2 * 16 + aRow;
                const uint32_t sw = (uint32_t)((rowB * 128 + cb) ^ ((rowB & 7) << 4));
                LDMX4(bh[nt2][0], bh[nt2][1], bh[nt2][2], bh[nt2][3], stB + sw);
            }
            #pragma unroll
            for (int mt = 0; mt < 4; mt++) {
                const int rowA = wm0 + mt * 16 + aRow;
                const uint32_t sw = (uint32_t)((rowA * 128 + cb) ^ ((rowA & 7) << 4));
                uint32_t a0, a1, a2, a3;
                LDMX4(a0, a1, a2, a3, stA + sw);
                #pragma unroll
                for (int nt = 0; nt < 8; nt++)
                    MMA16816(acc[mt][nt], a0, a1, a2, a3,
                             bh[nt >> 1][nt & 1], bh[nt >> 1][(nt & 1) + 2]);
            }
        }
        buf  = (buf  == NSTAGE - 1) ? 0 : buf + 1;
        bufw = (bufw == NSTAGE - 1) ? 0 : bufw + 1;
    }

    // ---- epilogue ----
    const int g  = lane >> 2;
    const int tg = lane & 3;
    #pragma unroll
    for (int mt = 0; mt < 4; mt++) {
        #pragma unroll
        for (int nt = 0; nt < 8; nt++) {
            const int col = bn + wn0 + nt * 8 + tg * 2;
            const float bx = bias[col], by = bias[col + 1];
            #pragma unroll
            for (int hh = 0; hh < 2; hh++) {
                const int row = bm + wm0 + mt * 16 + g + hh * 8;
                float v0 = acc[mt][nt][hh * 2 + 0] + bx;
                float v1 = acc[mt][nt][hh * 2 + 1] + by;
                if (epi == 4) {
                    v0 = 0.5f * v0 * (1.0f + erff(v0 * 0.7071067811865475f));
                    v1 = 0.5f * v1 * (1.0f + erff(v1 * 0.7071067811865475f));
                }
                if (epi == 2) {
                    const float2 rv = *(const float2*)&R[(size_t)row * N + col];
                    v0 += rv.x; v1 += rv.y;
                    float2 o; o.x = v0; o.y = v1;
                    *(float2*)&C[(size_t)row * N + col] = o;
                } else {
                    if (epi == 3 && col < DMODEL) {
                        v0 *= QSCALE; v1 *= QSCALE;
                    }
                    *(__half2*)&Ch[(size_t)row * N + col] = __floats2half2_rn(v0, v1);
                }
            }
        }
    }
}

// ---------------- tensor-core causal flash attention ----------------
// Balanced pairing (q-tile i and NQT-1-i per CTA), q-tile 128 (8 warps),
// key chunk 128, double-buffered K/V, base-2 softmax with ex2.approx.f16x2,
// row-sum l accumulated via ones-column MMA, diagonal chunk peeled.
#define QS 72
#define ATTN_Q_OFF 0
#define ATTN_K_OFF (128 * QS)
#define ATTN_V_OFF (3 * 128 * QS)
#define ATTN_SMEM_BYTES (5 * 128 * QS * 2)   // 92160
#define NQT (SEQ / 128)                      // 16

__global__ __launch_bounds__(256) void attn_tc(const __half* __restrict__ QKVh,
                                               __half* __restrict__ Oh) {
    extern __shared__ __half asm16[];

    const int bh = blockIdx.y;
    const int b  = bh >> 4;
    const int h  = bh & 15;
    const int tid  = threadIdx.x;
    const int wq   = tid >> 5;
    const int lane = tid & 31;
    const int g  = lane >> 2;
    const int tg = lane & 3;

    const __half* Kg = QKVh + (size_t)b * SEQ * QKVW + DMODEL + h * HDIM;
    const __half* Vg = Kg + DMODEL;

    const uint32_t qB = (uint32_t)__cvta_generic_to_shared(asm16) + ATTN_Q_OFF * 2;
    const uint32_t kB = (uint32_t)__cvta_generic_to_shared(asm16) + ATTN_K_OFF * 2;
    const uint32_t vB = (uint32_t)__cvta_generic_to_shared(asm16) + ATTN_V_OFF * 2;
    const uint32_t bufStride = 128 * QS * 2;

    for (int pass = 0; pass < 2; pass++) {
        const int qi = pass == 0 ? blockIdx.x : (NQT - 1 - blockIdx.x);
        const int q0 = qi * 128;
        const int nchunks = qi + 1;

        const __half* Qg = QKVh + ((size_t)b * SEQ + q0) * QKVW + h * HDIM;

        #pragma unroll
        for (int i = 0; i < 4; i++) {
            int idx = tid + i * 256;
            int r = idx >> 3, sg = (idx & 7) * 8;
            CP16(qB + (r * QS + sg) * 2, Qg + (size_t)r * QKVW + sg);
            CP16(kB + (r * QS + sg) * 2, Kg + (size_t)r * QKVW + sg);
            CP16(vB + (r * QS + sg) * 2, Vg + (size_t)r * QKVW + sg);
        }
        COMMIT();

        uint32_t Qa[4][4];
        float    o[8][4];
        float    lacc[4] = {0.f, 0.f, 0.f, 0.f};
        #pragma unroll
        for (int i = 0; i < 8; i++)
            #pragma unroll
            for (int j = 0; j < 4; j++) o[i][j] = 0.f;
        float m0 = -1e30f, m1 = -1e30f;

        // ---- main loop: chunks [0, nchunks-1), no masking ----
        for (int it = 0; it < nchunks - 1; it++) {
            const int buf = it & 1;
            {
                const int c1 = (it + 1) << 7;
                #pragma unroll
                for (int i = 0; i < 4; i++) {
                    int idx = tid + i * 256;
                    int r = idx >> 3, sg = (idx & 7) * 8;
                    CP16(kB + (buf ^ 1) * bufStride + (r * QS + sg) * 2, Kg + (size_t)(c1 + r) * QKVW + sg);
                    CP16(vB + (buf ^ 1) * bufStride + (r * QS + sg) * 2, Vg + (size_t)(c1 + r) * QKVW + sg);
                }
                COMMIT();
                asm volatile("cp.async.wait_group 1;\n" ::);
            }
            __syncthreads();

            if (it == 0) {
                #pragma unroll
                for (int kk = 0; kk < 4; kk++) {
                    uint32_t addr = qB + ((wq * 16 + (lane & 15)) * QS + kk * 16 + ((lane >> 4) << 3)) * 2;
                    LDMX4(Qa[kk][0], Qa[kk][1], Qa[kk][2], Qa[kk][3], addr);
                }
            }

            float s[16][4];
            #pragma unroll
            for (int i = 0; i < 16; i++)
                #pragma unroll
                for (int j = 0; j < 4; j++) s[i][j] = 0.f;

            #pragma unroll
            for (int kk = 0; kk < 4; kk++) {
                #pragma unroll
                for (int nt2 = 0; nt2 < 8; nt2++) {
                    uint32_t r0, r1, r2, r3;
                    uint32_t addr = kB + buf * bufStride +
                        ((nt2 * 16 + (lane & 15)) * QS + kk * 16 + ((lane >> 4) << 3)) * 2;
                    LDMX4(r0, r1, r2, r3, addr);
                    MMA16816(s[nt2 * 2],     Qa[kk][0], Qa[kk][1], Qa[kk][2], Qa[kk][3], r0, r2);
                    MMA16816(s[nt2 * 2 + 1], Qa[kk][0], Qa[kk][1], Qa[kk][2], Qa[kk][3], r1, r3);
                }
            }

            float mx0 = -1e30f, mx1 = -1e30f;
            #pragma unroll
            for (int nt = 0; nt < 16; nt++) {
                mx0 = fmaxf(mx0, fmaxf(s[nt][0], s[nt][1]));
                mx1 = fmaxf(mx1, fmaxf(s[nt][2], s[nt][3]));
            }
            mx0 = fmaxf(mx0, __shfl_xor_sync(0xffffffffu, mx0, 1));
            mx0 = fmaxf(mx0, __shfl_xor_sync(0xffffffffu, mx0, 2));
            mx1 = fmaxf(mx1, __shfl_xor_sync(0xffffffffu, mx1, 1));
            mx1 = fmaxf(mx1, __shfl_xor_sync(0xffffffffu, mx1, 2));
            const float mn0 = fmaxf(m0, mx0), mn1 = fmaxf(m1, mx1);
            const float cr0 = ex2f(m0 - mn0), cr1 = ex2f(m1 - mn1);
            m0 = mn0; m1 = mn1;

            // pack (s - max) to half2, exp via f16x2 MUFU -> P fragments
            uint32_t ph[16][2];
            #pragma unroll
            for (int nt = 0; nt < 16; nt++) {
                ph[nt][0] = h2ex2(packh2(s[nt][0] - mn0, s[nt][1] - mn0));
                ph[nt][1] = h2ex2(packh2(s[nt][2] - mn1, s[nt][3] - mn1));
            }

            #pragma unroll
            for (int nd = 0; nd < 8; nd++) {
                o[nd][0] *= cr0; o[nd][1] *= cr0;
                o[nd][2] *= cr1; o[nd][3] *= cr1;
            }
            lacc[0] *= cr0; lacc[1] *= cr0;
            lacc[2] *= cr1; lacc[3] *= cr1;

            #pragma unroll
            for (int kk = 0; kk < 8; kk++) {
                const uint32_t pa0 = ph[2*kk][0],   pa1 = ph[2*kk][1];
                const uint32_t pa2 = ph[2*kk+1][0], pa3 = ph[2*kk+1][1];
                MMA16816(lacc, pa0, pa1, pa2, pa3, ONES_H2, ONES_H2);
                #pragma unroll
                for (int nd2 = 0; nd2 < 4; nd2++) {
                    uint32_t r0, r1, r2, r3;
                    uint32_t addr = vB + buf * bufStride +
                        ((kk * 16 + (lane & 15)) * QS + nd2 * 16 + ((lane >> 4) << 3)) * 2;
                    LDMX4T(r0, r1, r2, r3, addr);
                    MMA16816(o[nd2 * 2],     pa0, pa1, pa2, pa3, r0, r1);
                    MMA16816(o[nd2 * 2 + 1], pa0, pa1, pa2, pa3, r2, r3);
                }
            }
            __syncthreads();
        }

        // ---- peeled diagonal chunk ----
        {
            const int buf = (nchunks - 1) & 1;
            asm volatile("cp.async.wait_group 0;\n" ::);
            __syncthreads();

            if (nchunks == 1) {
                #pragma unroll
                for (int kk = 0; kk < 4; kk++) {
                    uint32_t addr = qB + ((wq * 16 + (lane & 15)) * QS + kk * 16 + ((lane >> 4) << 3)) * 2;
                    LDMX4(Qa[kk][0], Qa[kk][1], Qa[kk][2], Qa[kk][3], addr);
                }
            }

            float s[16][4];
            #pragma unroll
            for (int i = 0; i < 16; i++)
                #pragma unroll
                for (int j = 0; j < 4; j++) s[i][j] = 0.f;

            #pragma unroll
            for (int kk = 0; kk < 4; kk++) {
                #pragma unroll
                for (int nt2 = 0; nt2 < 8; nt2++) {
                    if (nt2 > wq) continue;
                    uint32_t r0, r1, r2, r3;
                    uint32_t addr = kB + buf * bufStride +
                        ((nt2 * 16 + (lane & 15)) * QS + kk * 16 + ((lane >> 4) << 3)) * 2;
                    LDMX4(r0, r1, r2, r3, addr);
                    MMA16816(s[nt2 * 2],     Qa[kk][0], Qa[kk][1], Qa[kk][2], Qa[kk][3], r0, r2);
                    MMA16816(s[nt2 * 2 + 1], Qa[kk][0], Qa[kk][1], Qa[kk][2], Qa[kk][3], r1, r3);
                }
            }

            {
                const int row0a = wq * 16 + g;
                const int row1a = row0a + 8;
                #pragma unroll
                for (int nt = 0; nt < 16; nt++) {
                    const int key = nt * 8 + 2 * tg;
                    if (key     > row0a) s[nt][0] = -1e30f;
                    if (key + 1 > row0a) s[nt][1] = -1e30f;
                    if (key     > row1a) s[nt][2] = -1e30f;
                    if (key + 1 > row1a) s[nt][3] = -1e30f;
                }
            }

            float mx0 = -1e30f, mx1 = -1e30f;
            #pragma unroll
            for (int nt = 0; nt < 16; nt++) {
                mx0 = fmaxf(mx0, fmaxf(s[nt][0], s[nt][1]));
                mx1 = fmaxf(mx1, fmaxf(s[nt][2], s[nt][3]));
            }
            mx0 = fmaxf(mx0, __shfl_xor_sync(0xffffffffu, mx0, 1));
            mx0 = fmaxf(mx0, __shfl_xor_sync(0xffffffffu, mx0, 2));
            mx1 = fmaxf(mx1, __shfl_xor_sync(0xffffffffu, mx1, 1));
            mx1 = fmaxf(mx1, __shfl_xor_sync(0xffffffffu, mx1, 2));
            const float mn0 = fmaxf(m0, mx0), mn1 = fmaxf(m1, mx1);
            const float cr0 = ex2f(m0 - mn0), cr1 = ex2f(m1 - mn1);

            uint32_t ph[16][2];
            #pragma unroll
            for (int nt = 0; nt < 16; nt++) {
                ph[nt][0] = h2ex2(packh2(s[nt][0] - mn0, s[nt][1] - mn0));
                ph[nt][1] = h2ex2(packh2(s[nt][2] - mn1, s[nt][3] - mn1));
            }

            #pragma unroll
            for (int nd = 0; nd < 8; nd++) {
                o[nd][0] *= cr0; o[nd][1] *= cr0;
                o[nd][2] *= cr1; o[nd][3] *= cr1;
            }
            lacc[0] *= cr0; lacc[1] *= cr0;
            lacc[2] *= cr1; lacc[3] *= cr1;

            #pragma unroll
            for (int kk = 0; kk < 8; kk++) {
                if (kk > wq) continue;           // P exactly 0 above diagonal
                const uint32_t pa0 = ph[2*kk][0],   pa1 = ph[2*kk][1];
                const uint32_t pa2 = ph[2*kk+1][0], pa3 = ph[2*kk+1][1];
                MMA16816(lacc, pa0, pa1, pa2, pa3, ONES_H2, ONES_H2);
                #pragma unroll
                for (int nd2 = 0; nd2 < 4; nd2++) {
                    uint32_t r0, r1, r2, r3;
                    uint32_t addr = vB + buf * bufStride +
                        ((kk * 16 + (lane & 15)) * QS + nd2 * 16 + ((lane >> 4) << 3)) * 2;
                    LDMX4T(r0, r1, r2, r3, addr);
                    MMA16816(o[nd2 * 2],     pa0, pa1, pa2, pa3, r0, r1);
                    MMA16816(o[nd2 * 2 + 1], pa0, pa1, pa2, pa3, r2, r3);
                }
            }
        }

        // ---- epilogue for this q-tile ----
        const float inv0 = 1.f / lacc[0], inv1 = 1.f / lacc[2];
        const int row0 = q0 + wq * 16 + g;
        const size_t ob0 = ((size_t)b * SEQ + row0) * DMODEL + h * HDIM;
        const size_t ob1 = ob0 + 8 * DMODEL;
        #pragma unroll
        for (int nd = 0; nd < 8; nd++) {
            const int d = nd * 8 + 2 * tg;
            *(__half2*)&Oh[ob0 + d] = __floats2half2_rn(o[nd][0] * inv0, o[nd][1] * inv0);
            *(__half2*)&Oh[ob1 + d] = __floats2half2_rn(o[nd][2] * inv1, o[nd][3] * inv1);
        }
        __syncthreads();   // smem reuse safety before next pass
    }
}

// ---------------- launcher ----------------
extern "C" void kernel_launch(void* const* d_in, const int* in_sizes, int n_in,
                              void* d_out, int out_size) {
    const float* x     = (const float*)d_in[0];
    const float* Wq    = (const float*)d_in[2];
    const float* bq    = (const float*)d_in[3];
    const float* Wk    = (const float*)d_in[4];
    const float* bk    = (const float*)d_in[5];
    const float* Wv    = (const float*)d_in[6];
    const float* bv    = (const float*)d_in[7];
    const float* Wo    = (const float*)d_in[8];
    const float* bo    = (const float*)d_in[9];
    const float* W1    = (const float*)d_in[10];
    const float* b1    = (const float*)d_in[11];
    const float* W2    = (const float*)d_in[12];
    const float* b2    = (const float*)d_in[13];
    const float* g1    = (const float*)d_in[14];
    const float* beta1 = (const float*)d_in[15];
    const float* g2    = (const float*)d_in[16];
    const float* beta2 = (const float*)d_in[17];
    float* out = (float*)d_out;

    float *x2, *bqkv;
    __half *qkvh, *ah, *hh, *wh;
    cudaGetSymbolAddress((void**)&x2,   g_x2);
    cudaGetSymbolAddress((void**)&bqkv, g_bqkv);
    cudaGetSymbolAddress((void**)&qkvh, g_qkvh);
    cudaGetSymbolAddress((void**)&ah,   g_ah);
    cudaGetSymbolAddress((void**)&hh,   g_hh);
    cudaGetSymbolAddress((void**)&wh,   g_wh);

    static cudaStream_t s2 = nullptr;
    static cudaEvent_t eF, e1, e2, e3, e4;
    static bool init_done = false;
    if (!init_done) {
        cudaFuncSetAttribute(hgemm1t, cudaFuncAttributeMaxDynamicSharedMemorySize, GSMEM_BYTES);
        cudaFuncSetAttribute(attn_tc, cudaFuncAttributeMaxDynamicSharedMemorySize, ATTN_SMEM_BYTES);
        cudaStreamCreateWithFlags(&s2, cudaStreamNonBlocking);
        cudaEventCreateWithFlags(&eF, cudaEventDisableTiming);
        cudaEventCreateWithFlags(&e1, cudaEventDisableTiming);
        cudaEventCreateWithFlags(&e2, cudaEventDisableTiming);
        cudaEventCreateWithFlags(&e3, cudaEventDisableTiming);
        cudaEventCreateWithFlags(&e4, cudaEventDisableTiming);
        init_done = true;
    }

    const int M = MROWS, D = DMODEL, F = FFDIM;
    const size_t DD = (size_t)D * D;
    __half* wqkv = wh;
    __half* wo16 = wh + 3 * DD;
    __half* w116 = wh + 4 * DD;
    __half* w216 = wh + 8 * DD;

    // ---- fork side stream for weight conversions ----
    cudaEventRecord(eF, 0);
    cudaStreamWaitEvent(s2, eF, 0);
    cvt16<<<(int)(DD / 8) / 256, 256, 0, s2>>>(Wq, wqkv);
    cvt16<<<(int)(DD / 8) / 256, 256, 0, s2>>>(Wk, wqkv + DD);
    cvt16<<<(int)(DD / 8) / 256, 256, 0, s2>>>(Wv, wqkv + 2 * DD);
    pack_bias<<<QKVW / 256, 256, 0, s2>>>(bq, bk, bv, bqkv);
    cudaEventRecord(e1, s2);
    cvt16<<<(int)(DD / 8) / 256, 256, 0, s2>>>(Wo, wo16);
    cudaEventRecord(e2, s2);
    cvt16<<<(int)((size_t)F * D / 8) / 256, 256, 0, s2>>>(W1, w116);
    cudaEventRecord(e3, s2);
    cvt16<<<(int)((size_t)D * F / 8) / 256, 256, 0, s2>>>(W2, w216);
    cudaEventRecord(e4, s2);

    // ---- main stream ----
    ln_h16<<<M, 256>>>(x, g1, beta1, ah);

    cudaStreamWaitEvent(0, e1, 0);
    dim3 gQKV(QKVW / 128, M / 128);
    hgemm1t<<<gQKV, 128, GSMEM_BYTES>>>(ah, wqkv, bqkv, nullptr,
                                        nullptr, qkvh, M, QKVW, D, 3);

    dim3 gA(NQT / 2, BSZ * NHEADS);
    attn_tc<<<gA, 256, ATTN_SMEM_BYTES>>>(qkvh, ah);

    cudaStreamWaitEvent(0, e2, 0);
    dim3 gD(D / 128, M / 128);
    hgemm1t<<<gD, 128, GSMEM_BYTES>>>(ah, wo16, bo, x,
                                      x2, nullptr, M, D, D, 2);

    ln_h16<<<M, 256>>>(x2, g2, beta2, ah);

    cudaStreamWaitEvent(0, e3, 0);
    dim3 gF1(F / 128, M / 128);
    hgemm1t<<<gF1, 128, GSMEM_BYTES>>>(ah, w116, b1, nullptr,
                                       nullptr, hh, M, F, D, 4);

    cudaStreamWaitEvent(0, e4, 0);
    hgemm1t<<<gD, 128, GSMEM_BYTES>>>(hh, w216, b2, x2,
                                      out, nullptr, M, D, F, 2);
}